// round 2
// baseline (speedup 1.0000x reference)
#include <cuda_runtime.h>
#include <cuda_bf16.h>
#include <stdint.h>

#define NNODES 50000
#define NEDGES 600000

// ---------------- scratch (static device globals; no dynamic alloc) ----------
__device__ float g_x0[(size_t)NNODES * 128];
__device__ float g_x1[(size_t)NNODES * 128];
__device__ float g_x2[(size_t)NNODES * 128];
__device__ float g_x3[(size_t)NNODES * 128];
__device__ float g_xa[(size_t)NNODES * 384];
__device__ float g_wcat[384 * 128];
__device__ int   g_cnt[NNODES];
__device__ int   g_rowptr[NNODES + 1];
__device__ int   g_cursor[NNODES];
__device__ int   g_adj[NEDGES];

// ---------------- helpers ----------------------------------------------------
typedef unsigned long long ull;

__device__ __forceinline__ float lrelu(float x) { return x > 0.f ? x : 0.01f * x; }

__device__ __forceinline__ void ffma2(ull& d, ull a, ull b, ull c) {
    asm("fma.rn.f32x2 %0, %1, %2, %3;" : "=l"(d) : "l"(a), "l"(b), "l"(c));
}
__device__ __forceinline__ ull dup2(float x) {
    ull r; asm("mov.b64 %0, {%1, %1};" : "=l"(r) : "f"(x)); return r;
}
__device__ __forceinline__ float2 unpk(ull v) {
    float2 r; asm("mov.b64 {%0, %1}, %2;" : "=f"(r.x), "=f"(r.y) : "l"(v)); return r;
}

__device__ __forceinline__ void ldsm4(uint32_t* r, uint32_t addr) {
    asm volatile("ldmatrix.sync.aligned.m8n8.x4.shared.b16 {%0,%1,%2,%3}, [%4];"
                 : "=r"(r[0]), "=r"(r[1]), "=r"(r[2]), "=r"(r[3]) : "r"(addr));
}

__device__ __forceinline__ void mma16816(float* c, const uint32_t* a, const uint32_t* b) {
    asm volatile("mma.sync.aligned.m16n8k16.row.col.f32.bf16.bf16.f32 "
                 "{%0,%1,%2,%3}, {%4,%5,%6,%7}, {%8,%9}, {%0,%1,%2,%3};"
                 : "+f"(c[0]), "+f"(c[1]), "+f"(c[2]), "+f"(c[3])
                 : "r"(a[0]), "r"(a[1]), "r"(a[2]), "r"(a[3]),
                   "r"(b[0]), "r"(b[1]));
}

__device__ __forceinline__ void split_bf(float v, __nv_bfloat16& hi, __nv_bfloat16& lo) {
    hi = __float2bfloat16_rn(v);
    lo = __float2bfloat16_rn(v - __bfloat162float(hi));
}

// ---------------- tensor GEMM: C[M,128] = act(A[M,K] @ W[K,128] + b) ---------
// 3x K-expansion bf16 split: A' = [Ah | Al | Ah], B' = [Bh | Bh | Bl] along K
// => AhBh + AlBh + AhBl  (error ~2^-18 relative).
// BM=128, BN=128 (full), BK=16 logical (48 physical), 256 threads / 8 warps.
// Warp grid 2(M)x4(N): warp tile 64x32 -> 4 mtiles(16) x 4 ntiles(8).
__global__ __launch_bounds__(256) void tgemm128(
    const float* __restrict__ A, int lda,
    const float* __restrict__ W,           // [K,128] row-major
    const float* __restrict__ bias,        // [128]
    float* __restrict__ C,                 // [M,128]
    int M, int K, int relu)
{
    constexpr int PK = 56;                  // padded physical K stride (halves)
    __shared__ __nv_bfloat16 As[128 * PK];
    __shared__ __nv_bfloat16 Bs[128 * PK];  // B transposed: Bs[n][k']

    const int tid = threadIdx.x;
    const int lane = tid & 31;
    const int wid = tid >> 5;
    const int warp_m = wid & 1;             // 0..1
    const int warp_n = wid >> 1;            // 0..3
    const int bm = blockIdx.x * 128;

    float acc[4][4][4];
#pragma unroll
    for (int mt = 0; mt < 4; mt++)
#pragma unroll
        for (int nt = 0; nt < 4; nt++)
#pragma unroll
            for (int q = 0; q < 4; q++) acc[mt][nt][q] = 0.f;

    // A staging: thread -> (row = tid/2, half = tid&1 -> 8 floats)
    const int arow = tid >> 1;
    const int ahalf = tid & 1;
    const bool avalid = (bm + arow) < M;
    const float* abase = A + (size_t)(bm + arow) * lda + ahalf * 8;

    // B staging: thread -> (kk = tid/16, n0 = (tid&15)*8)
    const int bkk = tid >> 4;
    const int bn0 = (tid & 15) * 8;

    // ldmatrix lane addressing
    const int g = lane >> 3, r = lane & 7;
    const int a_row_l = warp_m * 64 + r + (g & 1) * 8;  // + mt*16
    const int a_col_l = (g >> 1) * 8;                   // + ks*16
    const int b_row_l = warp_n * 32 + r + (g >> 1) * 8; // + pair*16
    const int b_col_l = (g & 1) * 8;                    // + ks*16
    const uint32_t As_u = (uint32_t)__cvta_generic_to_shared(As);
    const uint32_t Bs_u = (uint32_t)__cvta_generic_to_shared(Bs);

    for (int k0 = 0; k0 < K; k0 += 16) {
        // ---- stage A (fp32 -> bf16 hi/lo, 3x expansion) ----
        float va[8];
#pragma unroll
        for (int j = 0; j < 8; j++) va[j] = 0.f;
        if (avalid) {
            float4 v0 = *reinterpret_cast<const float4*>(abase + k0);
            float4 v1 = *reinterpret_cast<const float4*>(abase + k0 + 4);
            va[0] = v0.x; va[1] = v0.y; va[2] = v0.z; va[3] = v0.w;
            va[4] = v1.x; va[5] = v1.y; va[6] = v1.z; va[7] = v1.w;
        }
        {
            __nv_bfloat16* Ar = As + arow * PK + ahalf * 8;
#pragma unroll
            for (int j = 0; j < 4; j++) {
                __nv_bfloat16 h0, l0, h1, l1;
                split_bf(va[2 * j], h0, l0);
                split_bf(va[2 * j + 1], h1, l1);
                __nv_bfloat162 hp; hp.x = h0; hp.y = h1;
                __nv_bfloat162 lp; lp.x = l0; lp.y = l1;
                *reinterpret_cast<__nv_bfloat162*>(Ar + 2 * j)      = hp;
                *reinterpret_cast<__nv_bfloat162*>(Ar + 16 + 2 * j) = lp;
                *reinterpret_cast<__nv_bfloat162*>(Ar + 32 + 2 * j) = hp;
            }
        }
        // ---- stage B (transpose + split) ----
        {
            const float* wp = W + (size_t)(k0 + bkk) * 128 + bn0;
            float4 w0 = *reinterpret_cast<const float4*>(wp);
            float4 w1 = *reinterpret_cast<const float4*>(wp + 4);
            float wv[8] = {w0.x, w0.y, w0.z, w0.w, w1.x, w1.y, w1.z, w1.w};
#pragma unroll
            for (int j = 0; j < 8; j++) {
                __nv_bfloat16 h, l;
                split_bf(wv[j], h, l);
                __nv_bfloat16* Br = Bs + (bn0 + j) * PK;
                Br[bkk] = h;
                Br[16 + bkk] = h;
                Br[32 + bkk] = l;
            }
        }
        __syncthreads();

        // ---- MMA over the 3 physical k16 steps ----
#pragma unroll
        for (int ks = 0; ks < 3; ks++) {
            uint32_t af[4][4];
#pragma unroll
            for (int mt = 0; mt < 4; mt++)
                ldsm4(af[mt], As_u + (uint32_t)(((a_row_l + mt * 16) * PK
                                                 + a_col_l + ks * 16) * 2));
            uint32_t bf[2][4];
#pragma unroll
            for (int p = 0; p < 2; p++)
                ldsm4(bf[p], Bs_u + (uint32_t)(((b_row_l + p * 16) * PK
                                                 + b_col_l + ks * 16) * 2));
#pragma unroll
            for (int mt = 0; mt < 4; mt++)
#pragma unroll
                for (int nt = 0; nt < 4; nt++)
                    mma16816(acc[mt][nt], af[mt], &bf[nt >> 1][(nt & 1) * 2]);
        }
        __syncthreads();
    }

    // ---- epilogue: bias (+ lrelu) -> C ----
    const int qr = lane >> 2;
    const int qc = (lane & 3) * 2;
#pragma unroll
    for (int nt = 0; nt < 4; nt++) {
        const int col = warp_n * 32 + nt * 8 + qc;
        const float b0 = bias[col];
        const float b1 = bias[col + 1];
#pragma unroll
        for (int mt = 0; mt < 4; mt++) {
            int r0 = bm + warp_m * 64 + mt * 16 + qr;
            float o0 = acc[mt][nt][0] + b0;
            float o1 = acc[mt][nt][1] + b1;
            float o2 = acc[mt][nt][2] + b0;
            float o3 = acc[mt][nt][3] + b1;
            if (relu) { o0 = lrelu(o0); o1 = lrelu(o1); o2 = lrelu(o2); o3 = lrelu(o3); }
            if (r0 < M) {
                float2 v; v.x = o0; v.y = o1;
                *reinterpret_cast<float2*>(C + (size_t)r0 * 128 + col) = v;
            }
            if (r0 + 8 < M) {
                float2 v; v.x = o2; v.y = o3;
                *reinterpret_cast<float2*>(C + (size_t)(r0 + 8) * 128 + col) = v;
            }
        }
    }
}

// ---------------- fp32 FFMA2 GEMM (kept for des/tweet, K=768, NC<=32) --------
template <int BN>
__global__ __launch_bounds__(256) void gemm_kernel(
    const float* __restrict__ A, int lda,
    const float* __restrict__ W, int ldw,
    const float* __restrict__ bias,
    float* __restrict__ C, int ldc, int col_off,
    int M, int K, int NC, int relu)
{
    constexpr int BM = 128, BK = 16;
    constexpr int NTX = BN / 4;
    constexpr int NTY = 256 / NTX;
    constexpr int TM  = BM / NTY;
    constexpr int NPAIR = TM / 2;

    __shared__ float As[BK][BM];
    __shared__ float Bs[BK][BN];

    const int tid = threadIdx.x;
    const int tx = tid % NTX, ty = tid / NTX;
    const int bm = blockIdx.x * BM;
    const int bn = blockIdx.y * BN;

    ull acc[NPAIR][4];
#pragma unroll
    for (int p = 0; p < NPAIR; p++)
#pragma unroll
        for (int j = 0; j < 4; j++) acc[p][j] = 0ull;

    for (int k0 = 0; k0 < K; k0 += BK) {
#pragma unroll
        for (int i = 0; i < 2; i++) {
            int idx = tid * 2 + i;
            int row = idx >> 2;
            int kq = (idx & 3) << 2;
            float4 v = make_float4(0.f, 0.f, 0.f, 0.f);
            int gr = bm + row;
            if (gr < M)
                v = *reinterpret_cast<const float4*>(A + (size_t)gr * lda + k0 + kq);
            As[kq + 0][row] = v.x;
            As[kq + 1][row] = v.y;
            As[kq + 2][row] = v.z;
            As[kq + 3][row] = v.w;
        }
        constexpr int EB = (BK * BN) / 256;
#pragma unroll
        for (int i = 0; i < EB; i++) {
            int idx = tid * EB + i;
            int krow = idx / BN;
            int col = idx % BN;
            int gc = bn + col;
            float v = 0.f;
            if (gc < NC) v = W[(size_t)(k0 + krow) * ldw + gc];
            Bs[krow][col] = v;
        }
        __syncthreads();

#pragma unroll
        for (int kk = 0; kk < BK; kk++) {
            const float* ap = &As[kk][ty * TM];
            ull a[NPAIR];
#pragma unroll
            for (int p = 0; p < NPAIR; p++)
                a[p] = *reinterpret_cast<const ull*>(ap + 2 * p);
            float4 bf = *reinterpret_cast<const float4*>(&Bs[kk][tx * 4]);
            ull b0 = dup2(bf.x), b1 = dup2(bf.y), b2 = dup2(bf.z), b3 = dup2(bf.w);
#pragma unroll
            for (int p = 0; p < NPAIR; p++) {
                ffma2(acc[p][0], a[p], b0, acc[p][0]);
                ffma2(acc[p][1], a[p], b1, acc[p][1]);
                ffma2(acc[p][2], a[p], b2, acc[p][2]);
                ffma2(acc[p][3], a[p], b3, acc[p][3]);
            }
        }
        __syncthreads();
    }

    float bv[4];
#pragma unroll
    for (int j = 0; j < 4; j++) {
        int gc = bn + tx * 4 + j;
        bv[j] = (gc < NC) ? bias[gc] : 0.f;
    }
#pragma unroll
    for (int p = 0; p < NPAIR; p++) {
#pragma unroll
        for (int j = 0; j < 4; j++) {
            int gc = bn + tx * 4 + j;
            if (gc < NC) {
                float2 v = unpk(acc[p][j]);
                float o0 = v.x + bv[j];
                float o1 = v.y + bv[j];
                if (relu) { o0 = lrelu(o0); o1 = lrelu(o1); }
                int r0 = bm + ty * TM + 2 * p;
                if (r0 < M)     C[(size_t)r0 * ldc + col_off + gc] = o0;
                if (r0 + 1 < M) C[(size_t)(r0 + 1) * ldc + col_off + gc] = o1;
            }
        }
    }
}

// ---------------- small-K feature columns (num/cat/new -> x0 cols 53..127) ---
__global__ void feat_small_kernel(
    const float* __restrict__ numf, const float* __restrict__ catf,
    const float* __restrict__ nf,
    const float* __restrict__ Wn, const float* __restrict__ bn,
    const float* __restrict__ Wc, const float* __restrict__ bc,
    const float* __restrict__ Ww, const float* __restrict__ bw,
    float* __restrict__ x0)
{
    __shared__ float sWn[7 * 25], sbn[25], sWc[11 * 25], sbc[25], sWw[25], sbw[25];
    int tid = threadIdx.x;
    for (int i = tid; i < 7 * 25; i += blockDim.x) sWn[i] = Wn[i];
    for (int i = tid; i < 11 * 25; i += blockDim.x) sWc[i] = Wc[i];
    for (int i = tid; i < 25; i += blockDim.x) {
        sbn[i] = bn[i]; sbc[i] = bc[i]; sWw[i] = Ww[i]; sbw[i] = bw[i];
    }
    __syncthreads();

    int r = blockIdx.x * blockDim.x + tid;
    if (r >= NNODES) return;

    float nv[7], cv[11];
#pragma unroll
    for (int k = 0; k < 7; k++) nv[k] = numf[(size_t)r * 7 + k];
#pragma unroll
    for (int k = 0; k < 11; k++) cv[k] = catf[(size_t)r * 11 + k];
    float wv = nf[r];

    float* out = x0 + (size_t)r * 128;
#pragma unroll
    for (int j = 0; j < 25; j++) {
        float a = sbn[j];
#pragma unroll
        for (int k = 0; k < 7; k++) a += nv[k] * sWn[k * 25 + j];
        out[53 + j] = lrelu(a);
    }
#pragma unroll
    for (int j = 0; j < 25; j++) {
        float a = sbc[j];
#pragma unroll
        for (int k = 0; k < 11; k++) a += cv[k] * sWc[k * 25 + j];
        out[78 + j] = lrelu(a);
    }
#pragma unroll
    for (int j = 0; j < 25; j++)
        out[103 + j] = lrelu(wv * sWw[j] + sbw[j]);
}

// ---------------- CSR build ---------------------------------------------------
__global__ void zero_cnt_kernel() {
    int i = blockIdx.x * blockDim.x + threadIdx.x;
    if (i < NNODES) g_cnt[i] = 0;
}

__global__ void hist_kernel(const int* __restrict__ ei) {
    int e = blockIdx.x * blockDim.x + threadIdx.x;
    if (e < NEDGES) atomicAdd(&g_cnt[ei[NEDGES + e]], 1);
}

__global__ void scan_kernel() {
    __shared__ int wsum[32];
    __shared__ int carry;
    int tid = threadIdx.x, lane = tid & 31, wid = tid >> 5;
    if (tid == 0) carry = 0;
    __syncthreads();
    for (int base = 0; base < NNODES; base += 1024) {
        int i = base + tid;
        int v = (i < NNODES) ? g_cnt[i] : 0;
        int x = v;
#pragma unroll
        for (int o = 1; o < 32; o <<= 1) {
            int y = __shfl_up_sync(0xffffffffu, x, o);
            if (lane >= o) x += y;
        }
        if (lane == 31) wsum[wid] = x;
        __syncthreads();
        if (wid == 0) {
            int s = wsum[lane];
#pragma unroll
            for (int o = 1; o < 32; o <<= 1) {
                int y = __shfl_up_sync(0xffffffffu, s, o);
                if (lane >= o) s += y;
            }
            wsum[lane] = s;
        }
        __syncthreads();
        int c = carry;
        int woff = wid ? wsum[wid - 1] : 0;
        int excl = c + woff + x - v;
        if (i < NNODES) { g_rowptr[i] = excl; g_cursor[i] = excl; }
        int total = wsum[31];
        __syncthreads();
        if (tid == 0) carry = c + total;
        __syncthreads();
    }
    if (threadIdx.x == 0) g_rowptr[NNODES] = NEDGES;
}

__global__ void fill_kernel(const int* __restrict__ ei, const int* __restrict__ et) {
    int e = blockIdx.x * blockDim.x + threadIdx.x;
    if (e < NEDGES) {
        int s = ei[e];
        int d = ei[NEDGES + e];
        int t = et[e];
        int p = atomicAdd(&g_cursor[d], 1);
        g_adj[p] = s | (t << 30);
    }
}

// ---------------- aggregation: xa = [aggA/deg | aggB/deg | x] ----------------
__global__ void aggregate_kernel(const float* __restrict__ xin, float* __restrict__ xa) {
    int w = (blockIdx.x * blockDim.x + threadIdx.x) >> 5;
    int lane = threadIdx.x & 31;
    if (w >= NNODES) return;
    int beg = g_rowptr[w], end = g_rowptr[w + 1];
    float4 aA = make_float4(0.f, 0.f, 0.f, 0.f);
    float4 aB = make_float4(0.f, 0.f, 0.f, 0.f);
    for (int e = beg; e < end; e++) {
        int pk = g_adj[e];
        int src = pk & 0x3FFFFFFF;
        float4 v = *reinterpret_cast<const float4*>(xin + (size_t)src * 128 + lane * 4);
        if (pk >> 30) { aB.x += v.x; aB.y += v.y; aB.z += v.z; aB.w += v.w; }
        else          { aA.x += v.x; aA.y += v.y; aA.z += v.z; aA.w += v.w; }
    }
    int deg = end - beg;
    float s = 1.f / (float)(deg > 0 ? deg : 1);
    float4 xv = *reinterpret_cast<const float4*>(xin + (size_t)w * 128 + lane * 4);
    float* o = xa + (size_t)w * 384 + lane * 4;
    float4 oa = make_float4(aA.x * s, aA.y * s, aA.z * s, aA.w * s);
    float4 ob = make_float4(aB.x * s, aB.y * s, aB.z * s, aB.w * s);
    *reinterpret_cast<float4*>(o) = oa;
    *reinterpret_cast<float4*>(o + 128) = ob;
    *reinterpret_cast<float4*>(o + 256) = xv;
}

// ---------------- wcat = [rel_w0; rel_w1; root_w] (384x128) ------------------
__global__ void build_wcat_kernel(const float* __restrict__ relw,
                                  const float* __restrict__ rootw) {
    int i = blockIdx.x * blockDim.x + threadIdx.x;
    if (i < 32768) g_wcat[i] = relw[i];
    else if (i < 49152) g_wcat[i] = rootw[i - 32768];
}

// ---------------- final: out = x @ W_out2 + b_out2 (N x 2) -------------------
__global__ void final_kernel(const float* __restrict__ x,
                             const float* __restrict__ W,
                             const float* __restrict__ b,
                             float* __restrict__ out) {
    __shared__ float w[256];
    __shared__ float bb[2];
    int tid = threadIdx.x;
    for (int i = tid; i < 256; i += blockDim.x) w[i] = W[i];
    if (tid < 2) bb[tid] = b[tid];
    __syncthreads();
    int r = blockIdx.x * blockDim.x + tid;
    if (r >= NNODES) return;
    float a0 = bb[0], a1 = bb[1];
    const float4* xr = reinterpret_cast<const float4*>(x + (size_t)r * 128);
#pragma unroll
    for (int k4 = 0; k4 < 32; k4++) {
        float4 v = xr[k4];
        int k = k4 * 4;
        a0 += v.x * w[2 * k + 0]; a1 += v.x * w[2 * k + 1];
        a0 += v.y * w[2 * k + 2]; a1 += v.y * w[2 * k + 3];
        a0 += v.z * w[2 * k + 4]; a1 += v.z * w[2 * k + 5];
        a0 += v.w * w[2 * k + 6]; a1 += v.w * w[2 * k + 7];
    }
    out[(size_t)r * 2 + 0] = a0;
    out[(size_t)r * 2 + 1] = a1;
}

// ---------------- launch ------------------------------------------------------
extern "C" void kernel_launch(void* const* d_in, const int* in_sizes, int n_in,
                              void* d_out, int out_size)
{
    const bool setup_order = (in_sizes[5] == 2 * NEDGES);

    const float* des   = (const float*)d_in[0];
    const float* tweet = (const float*)d_in[1];
    const float* numf  = (const float*)d_in[2];
    const float* catf  = (const float*)d_in[3];
    const float* nf    = (const float*)d_in[4];
    const int* ei;
    const int* et;
    int wbase;
    if (setup_order) { ei = (const int*)d_in[5]; et = (const int*)d_in[6]; wbase = 7; }
    else             { ei = (const int*)d_in[27]; et = (const int*)d_in[28]; wbase = 5; }

#define WI(k) ((const float*)d_in[wbase + (k)])
    const float* W_des   = WI(0);  const float* b_des   = WI(1);
    const float* W_tweet = WI(2);  const float* b_tweet = WI(3);
    const float* W_num   = WI(4);  const float* b_num   = WI(5);
    const float* W_cat   = WI(6);  const float* b_cat   = WI(7);
    const float* W_new   = WI(8);  const float* b_new   = WI(9);
    const float* W_in    = WI(10); const float* b_in    = WI(11);
    const float* rel_w1  = WI(12); const float* root_w1 = WI(13); const float* bias1 = WI(14);
    const float* rel_w2  = WI(15); const float* root_w2 = WI(16); const float* bias2 = WI(17);
    const float* W_out1  = WI(18); const float* b_out1  = WI(19);
    const float* W_out2  = WI(20); const float* b_out2  = WI(21);
#undef WI

    float *x0, *x1, *x2, *x3, *xa, *wcat;
    cudaGetSymbolAddress((void**)&x0, g_x0);
    cudaGetSymbolAddress((void**)&x1, g_x1);
    cudaGetSymbolAddress((void**)&x2, g_x2);
    cudaGetSymbolAddress((void**)&x3, g_x3);
    cudaGetSymbolAddress((void**)&xa, g_xa);
    cudaGetSymbolAddress((void**)&wcat, g_wcat);

    const int MB = (NNODES + 127) / 128;  // 391

    // Feature transforms -> x0 [N,128]
    feat_small_kernel<<<(NNODES + 255) / 256, 256>>>(
        numf, catf, nf, W_num, b_num, W_cat, b_cat, W_new, b_new, x0);
    gemm_kernel<32><<<dim3(MB, 1), 256>>>(des, 768, W_des, 25, b_des,
                                          x0, 128, 0, NNODES, 768, 25, 1);
    gemm_kernel<32><<<dim3(MB, 1), 256>>>(tweet, 768, W_tweet, 28, b_tweet,
                                          x0, 128, 25, NNODES, 768, 28, 1);
    // x1 = lrelu(x0 @ W_in + b_in)   (tensor)
    tgemm128<<<MB, 256>>>(x0, 128, W_in, b_in, x1, NNODES, 128, 1);

    // CSR by destination (shared by both RGCN layers)
    zero_cnt_kernel<<<(NNODES + 255) / 256, 256>>>();
    hist_kernel<<<(NEDGES + 255) / 256, 256>>>(ei);
    scan_kernel<<<1, 1024>>>();
    fill_kernel<<<(NEDGES + 255) / 256, 256>>>(ei, et);

    const int AGG_BLOCKS = (NNODES * 32 + 255) / 256;

    // RGCN layer 1
    build_wcat_kernel<<<192, 256>>>(rel_w1, root_w1);
    aggregate_kernel<<<AGG_BLOCKS, 256>>>(x1, xa);
    tgemm128<<<MB, 256>>>(xa, 384, wcat, bias1, x2, NNODES, 384, 0);

    // RGCN layer 2
    build_wcat_kernel<<<192, 256>>>(rel_w2, root_w2);
    aggregate_kernel<<<AGG_BLOCKS, 256>>>(x2, xa);
    tgemm128<<<MB, 256>>>(xa, 384, wcat, bias2, x3, NNODES, 384, 0);

    // Head
    tgemm128<<<MB, 256>>>(x3, 128, W_out1, b_out1, x1, NNODES, 128, 1);
    final_kernel<<<(NNODES + 255) / 256, 256>>>(x1, W_out2, b_out2, (float*)d_out);
}

// round 4
// speedup vs baseline: 1.2553x; 1.2553x over previous
#include <cuda_runtime.h>
#include <stdint.h>

#define NNODES 50000
#define NEDGES 600000

// ---------------- scratch (static device globals; no dynamic alloc) ----------
__device__ float g_x0[(size_t)NNODES * 128];
__device__ float g_x1[(size_t)NNODES * 128];
__device__ float g_x2[(size_t)NNODES * 128];
__device__ float g_x3[(size_t)NNODES * 128];
__device__ float g_xa[(size_t)NNODES * 384];
__device__ float g_wcat[384 * 128];
__device__ float g_wpad[2 * 768 * 32];
__device__ int   g_cnt[NNODES];
__device__ int   g_rowptr[NNODES + 1];
__device__ int   g_cursor[NNODES];
__device__ int   g_adj[NEDGES];

// ---------------- helpers ----------------------------------------------------
typedef unsigned long long ull;

__device__ __forceinline__ float lrelu(float x) { return x > 0.f ? x : 0.01f * x; }

__device__ __forceinline__ void ffma2(ull& d, ull a, ull b, ull c) {
    asm("fma.rn.f32x2 %0, %1, %2, %3;" : "=l"(d) : "l"(a), "l"(b), "l"(c));
}
__device__ __forceinline__ ull dup2(float x) {
    ull r; asm("mov.b64 %0, {%1, %1};" : "=l"(r) : "f"(x)); return r;
}
__device__ __forceinline__ float2 unpk(ull v) {
    float2 r; asm("mov.b64 {%0, %1}, %2;" : "=f"(r.x), "=f"(r.y) : "l"(v)); return r;
}

__device__ __forceinline__ void cp_async16(uint32_t smem, const void* gptr, int bytes) {
    asm volatile("cp.async.cg.shared.global [%0], [%1], 16, %2;"
                 :: "r"(smem), "l"(gptr), "r"(bytes) : "memory");
}
__device__ __forceinline__ void cp_commit() {
    asm volatile("cp.async.commit_group;" ::: "memory");
}
template <int N>
__device__ __forceinline__ void cp_wait() {
    asm volatile("cp.async.wait_group %0;" :: "n"(N) : "memory");
}

// ---------------- streaming GEMM for des/tweet (K=768, NC<=32) ---------------
// BM=128, BK=32, 256 threads, 2-stage cp.async pipeline.
// x-grid: row blocks; y-grid: 0=des(25 cols @0), 1=tweet(28 cols @25).
__global__ __launch_bounds__(256) void stream_gemm(
    const float* __restrict__ A0, const float* __restrict__ A1,
    const float* __restrict__ bias0, const float* __restrict__ bias1,
    float* __restrict__ C)
{
    constexpr int K = 768, BM = 128, BK = 32, LDA = 36;  // 36 floats = 144B row
    __shared__ float As[2][BM * LDA];
    __shared__ float Bs[2][BK * 32];

    const int y = blockIdx.y;
    const float* A    = y ? A1 : A0;
    const float* bias = y ? bias1 : bias0;
    const float* Wp   = g_wpad + y * (768 * 32);
    const int col_off = y ? 25 : 0;
    const int NC      = y ? 28 : 25;

    const int tid = threadIdx.x;
    const int tx = tid & 7;        // col group (4 cols)
    const int ty = tid >> 3;       // 0..31; rows = ty + 32*i
    const int bm = blockIdx.x * BM;

    uint32_t as_u[2], bs_u[2];
    as_u[0] = (uint32_t)__cvta_generic_to_shared(&As[0][0]);
    as_u[1] = (uint32_t)__cvta_generic_to_shared(&As[1][0]);
    bs_u[0] = (uint32_t)__cvta_generic_to_shared(&Bs[0][0]);
    bs_u[1] = (uint32_t)__cvta_generic_to_shared(&Bs[1][0]);

    ull acc[4][2];
#pragma unroll
    for (int i = 0; i < 4; i++) { acc[i][0] = 0ull; acc[i][1] = 0ull; }

    auto stage = [&](int s, int k0) {
        // A: 128 rows x 32 floats = 1024 16B units
#pragma unroll
        for (int j = 0; j < 4; j++) {
            int unit = tid + j * 256;
            int row = unit >> 3;
            int seg = unit & 7;
            int gr = bm + row;
            cp_async16(as_u[s] + (uint32_t)(row * (LDA * 4) + seg * 16),
                       A + (size_t)gr * K + k0 + seg * 4,
                       gr < NNODES ? 16 : 0);
        }
        // B: 32 rows x 32 floats = 256 16B units
        {
            int kr = tid >> 3;
            int seg = tid & 7;
            cp_async16(bs_u[s] + (uint32_t)(kr * 128 + seg * 16),
                       Wp + (size_t)(k0 + kr) * 32 + seg * 4, 16);
        }
    };

    stage(0, 0);
    cp_commit();

    for (int c = 0; c < K / BK; c++) {
        const int s = c & 1;
        if (c + 1 < K / BK) {
            stage(s ^ 1, (c + 1) * BK);
            cp_commit();
            cp_wait<1>();
        } else {
            cp_wait<0>();
        }
        __syncthreads();

        const float* as = &As[s][0];
        const float* bs = &Bs[s][0];
#pragma unroll
        for (int kk = 0; kk < BK; kk++) {
            ull b01 = *reinterpret_cast<const ull*>(bs + kk * 32 + tx * 4);
            ull b23 = *reinterpret_cast<const ull*>(bs + kk * 32 + tx * 4 + 2);
#pragma unroll
            for (int i = 0; i < 4; i++) {
                float a = as[(ty + 32 * i) * LDA + kk];
                ull a2 = dup2(a);
                ffma2(acc[i][0], a2, b01, acc[i][0]);
                ffma2(acc[i][1], a2, b23, acc[i][1]);
            }
        }
        __syncthreads();
    }

    // epilogue
    float bv[4];
#pragma unroll
    for (int j = 0; j < 4; j++) {
        int gc = tx * 4 + j;
        bv[j] = (gc < NC) ? bias[gc] : 0.f;
    }
#pragma unroll
    for (int i = 0; i < 4; i++) {
        int row = bm + ty + 32 * i;
        if (row >= NNODES) continue;
        float2 v01 = unpk(acc[i][0]);
        float2 v23 = unpk(acc[i][1]);
        float o[4] = {v01.x, v01.y, v23.x, v23.y};
        float* cr = C + (size_t)row * 128 + col_off;
#pragma unroll
        for (int j = 0; j < 4; j++) {
            int gc = tx * 4 + j;
            if (gc < NC) cr[gc] = lrelu(o[j] + bv[j]);
        }
    }
}

// ---------------- pad W for streaming GEMM -----------------------------------
__global__ void pad_w_kernel(const float* __restrict__ Wd,
                             const float* __restrict__ Wt) {
    int i = blockIdx.x * blockDim.x + threadIdx.x;
    if (i >= 2 * 768 * 32) return;
    int which = i >= 768 * 32;
    int r = i - which * 768 * 32;
    int k = r >> 5, j = r & 31;
    float v = 0.f;
    if (!which) { if (j < 25) v = Wd[k * 25 + j]; }
    else        { if (j < 28) v = Wt[k * 28 + j]; }
    g_wpad[i] = v;
}

// ---------------- FFMA2 GEMM (W_in, RGCN, W_out1) ----------------------------
template <int BN>
__global__ __launch_bounds__(256) void gemm_kernel(
    const float* __restrict__ A, int lda,
    const float* __restrict__ W, int ldw,
    const float* __restrict__ bias,
    float* __restrict__ C, int ldc, int col_off,
    int M, int K, int NC, int relu)
{
    constexpr int BM = 128, BK = 16;
    constexpr int NTX = BN / 4;
    constexpr int NTY = 256 / NTX;
    constexpr int TM  = BM / NTY;
    constexpr int NPAIR = TM / 2;

    __shared__ float As[BK][BM];
    __shared__ float Bs[BK][BN];

    const int tid = threadIdx.x;
    const int tx = tid % NTX, ty = tid / NTX;
    const int bm = blockIdx.x * BM;
    const int bn = blockIdx.y * BN;

    ull acc[NPAIR][4];
#pragma unroll
    for (int p = 0; p < NPAIR; p++)
#pragma unroll
        for (int j = 0; j < 4; j++) acc[p][j] = 0ull;

    for (int k0 = 0; k0 < K; k0 += BK) {
#pragma unroll
        for (int i = 0; i < 2; i++) {
            int idx = tid * 2 + i;
            int row = idx >> 2;
            int kq = (idx & 3) << 2;
            float4 v = make_float4(0.f, 0.f, 0.f, 0.f);
            int gr = bm + row;
            if (gr < M)
                v = *reinterpret_cast<const float4*>(A + (size_t)gr * lda + k0 + kq);
            As[kq + 0][row] = v.x;
            As[kq + 1][row] = v.y;
            As[kq + 2][row] = v.z;
            As[kq + 3][row] = v.w;
        }
        constexpr int EB = (BK * BN) / 256;
#pragma unroll
        for (int i = 0; i < EB; i++) {
            int idx = tid * EB + i;
            int krow = idx / BN;
            int col = idx % BN;
            int gc = bn + col;
            float v = 0.f;
            if (gc < NC) v = W[(size_t)(k0 + krow) * ldw + gc];
            Bs[krow][col] = v;
        }
        __syncthreads();

#pragma unroll
        for (int kk = 0; kk < BK; kk++) {
            const float* ap = &As[kk][ty * TM];
            ull a[NPAIR];
#pragma unroll
            for (int p = 0; p < NPAIR; p++)
                a[p] = *reinterpret_cast<const ull*>(ap + 2 * p);
            float4 bf = *reinterpret_cast<const float4*>(&Bs[kk][tx * 4]);
            ull b0 = dup2(bf.x), b1 = dup2(bf.y), b2 = dup2(bf.z), b3 = dup2(bf.w);
#pragma unroll
            for (int p = 0; p < NPAIR; p++) {
                ffma2(acc[p][0], a[p], b0, acc[p][0]);
                ffma2(acc[p][1], a[p], b1, acc[p][1]);
                ffma2(acc[p][2], a[p], b2, acc[p][2]);
                ffma2(acc[p][3], a[p], b3, acc[p][3]);
            }
        }
        __syncthreads();
    }

    float bv[4];
#pragma unroll
    for (int j = 0; j < 4; j++) {
        int gc = bn + tx * 4 + j;
        bv[j] = (gc < NC) ? bias[gc] : 0.f;
    }
#pragma unroll
    for (int p = 0; p < NPAIR; p++) {
#pragma unroll
        for (int j = 0; j < 4; j++) {
            int gc = bn + tx * 4 + j;
            if (gc < NC) {
                float2 v = unpk(acc[p][j]);
                float o0 = v.x + bv[j];
                float o1 = v.y + bv[j];
                if (relu) { o0 = lrelu(o0); o1 = lrelu(o1); }
                int r0 = bm + ty * TM + 2 * p;
                if (r0 < M)     C[(size_t)r0 * ldc + col_off + gc] = o0;
                if (r0 + 1 < M) C[(size_t)(r0 + 1) * ldc + col_off + gc] = o1;
            }
        }
    }
}

// ---------------- small-K feature columns (num/cat/new -> x0 cols 53..127) ---
__global__ void feat_small_kernel(
    const float* __restrict__ numf, const float* __restrict__ catf,
    const float* __restrict__ nf,
    const float* __restrict__ Wn, const float* __restrict__ bn,
    const float* __restrict__ Wc, const float* __restrict__ bc,
    const float* __restrict__ Ww, const float* __restrict__ bw,
    float* __restrict__ x0)
{
    __shared__ float sWn[7 * 25], sbn[25], sWc[11 * 25], sbc[25], sWw[25], sbw[25];
    int tid = threadIdx.x;
    for (int i = tid; i < 7 * 25; i += blockDim.x) sWn[i] = Wn[i];
    for (int i = tid; i < 11 * 25; i += blockDim.x) sWc[i] = Wc[i];
    for (int i = tid; i < 25; i += blockDim.x) {
        sbn[i] = bn[i]; sbc[i] = bc[i]; sWw[i] = Ww[i]; sbw[i] = bw[i];
    }
    __syncthreads();

    int r = blockIdx.x * blockDim.x + tid;
    if (r >= NNODES) return;

    float nv[7], cv[11];
#pragma unroll
    for (int k = 0; k < 7; k++) nv[k] = numf[(size_t)r * 7 + k];
#pragma unroll
    for (int k = 0; k < 11; k++) cv[k] = catf[(size_t)r * 11 + k];
    float wv = nf[r];

    float* out = x0 + (size_t)r * 128;
#pragma unroll
    for (int j = 0; j < 25; j++) {
        float a = sbn[j];
#pragma unroll
        for (int k = 0; k < 7; k++) a += nv[k] * sWn[k * 25 + j];
        out[53 + j] = lrelu(a);
    }
#pragma unroll
    for (int j = 0; j < 25; j++) {
        float a = sbc[j];
#pragma unroll
        for (int k = 0; k < 11; k++) a += cv[k] * sWc[k * 25 + j];
        out[78 + j] = lrelu(a);
    }
#pragma unroll
    for (int j = 0; j < 25; j++)
        out[103 + j] = lrelu(wv * sWw[j] + sbw[j]);
}

// ---------------- CSR build ---------------------------------------------------
__global__ void zero_cnt_kernel() {
    int i = blockIdx.x * blockDim.x + threadIdx.x;
    if (i < NNODES) g_cnt[i] = 0;
}

__global__ void hist_kernel(const int* __restrict__ ei) {
    int e = blockIdx.x * blockDim.x + threadIdx.x;
    if (e < NEDGES) atomicAdd(&g_cnt[ei[NEDGES + e]], 1);
}

__global__ void scan_kernel() {
    __shared__ int wsum[32];
    __shared__ int carry;
    int tid = threadIdx.x, lane = tid & 31, wid = tid >> 5;
    if (tid == 0) carry = 0;
    __syncthreads();
    for (int base = 0; base < NNODES; base += 1024) {
        int i = base + tid;
        int v = (i < NNODES) ? g_cnt[i] : 0;
        int x = v;
#pragma unroll
        for (int o = 1; o < 32; o <<= 1) {
            int y = __shfl_up_sync(0xffffffffu, x, o);
            if (lane >= o) x += y;
        }
        if (lane == 31) wsum[wid] = x;
        __syncthreads();
        if (wid == 0) {
            int s = wsum[lane];
#pragma unroll
            for (int o = 1; o < 32; o <<= 1) {
                int y = __shfl_up_sync(0xffffffffu, s, o);
                if (lane >= o) s += y;
            }
            wsum[lane] = s;
        }
        __syncthreads();
        int c = carry;
        int woff = wid ? wsum[wid - 1] : 0;
        int excl = c + woff + x - v;
        if (i < NNODES) { g_rowptr[i] = excl; g_cursor[i] = excl; }
        int total = wsum[31];
        __syncthreads();
        if (tid == 0) carry = c + total;
        __syncthreads();
    }
    if (threadIdx.x == 0) g_rowptr[NNODES] = NEDGES;
}

__global__ void fill_kernel(const int* __restrict__ ei, const int* __restrict__ et) {
    int e = blockIdx.x * blockDim.x + threadIdx.x;
    if (e < NEDGES) {
        int s = ei[e];
        int d = ei[NEDGES + e];
        int t = et[e];
        int p = atomicAdd(&g_cursor[d], 1);
        g_adj[p] = s | (t << 30);
    }
}

// ---------------- aggregation: xa = [aggA/deg | aggB/deg | x] ----------------
__global__ void aggregate_kernel(const float* __restrict__ xin, float* __restrict__ xa) {
    int w = (blockIdx.x * blockDim.x + threadIdx.x) >> 5;
    int lane = threadIdx.x & 31;
    if (w >= NNODES) return;
    int beg = g_rowptr[w], end = g_rowptr[w + 1];
    float4 aA = make_float4(0.f, 0.f, 0.f, 0.f);
    float4 aB = make_float4(0.f, 0.f, 0.f, 0.f);
    for (int e = beg; e < end; e++) {
        int pk = g_adj[e];
        int src = pk & 0x3FFFFFFF;
        float4 v = *reinterpret_cast<const float4*>(xin + (size_t)src * 128 + lane * 4);
        if (pk >> 30) { aB.x += v.x; aB.y += v.y; aB.z += v.z; aB.w += v.w; }
        else          { aA.x += v.x; aA.y += v.y; aA.z += v.z; aA.w += v.w; }
    }
    int deg = end - beg;
    float s = 1.f / (float)(deg > 0 ? deg : 1);
    float4 xv = *reinterpret_cast<const float4*>(xin + (size_t)w * 128 + lane * 4);
    float* o = xa + (size_t)w * 384 + lane * 4;
    float4 oa = make_float4(aA.x * s, aA.y * s, aA.z * s, aA.w * s);
    float4 ob = make_float4(aB.x * s, aB.y * s, aB.z * s, aB.w * s);
    *reinterpret_cast<float4*>(o) = oa;
    *reinterpret_cast<float4*>(o + 128) = ob;
    *reinterpret_cast<float4*>(o + 256) = xv;
}

// ---------------- wcat = [rel_w0; rel_w1; root_w] (384x128) ------------------
__global__ void build_wcat_kernel(const float* __restrict__ relw,
                                  const float* __restrict__ rootw) {
    int i = blockIdx.x * blockDim.x + threadIdx.x;
    if (i < 32768) g_wcat[i] = relw[i];
    else if (i < 49152) g_wcat[i] = rootw[i - 32768];
}

// ---------------- final: out = x @ W_out2 + b_out2 (N x 2) -------------------
__global__ void final_kernel(const float* __restrict__ x,
                             const float* __restrict__ W,
                             const float* __restrict__ b,
                             float* __restrict__ out) {
    __shared__ float w[256];
    __shared__ float bb[2];
    int tid = threadIdx.x;
    for (int i = tid; i < 256; i += blockDim.x) w[i] = W[i];
    if (tid < 2) bb[tid] = b[tid];
    __syncthreads();
    int r = blockIdx.x * blockDim.x + tid;
    if (r >= NNODES) return;
    float a0 = bb[0], a1 = bb[1];
    const float4* xr = reinterpret_cast<const float4*>(x + (size_t)r * 128);
#pragma unroll
    for (int k4 = 0; k4 < 32; k4++) {
        float4 v = xr[k4];
        int k = k4 * 4;
        a0 += v.x * w[2 * k + 0]; a1 += v.x * w[2 * k + 1];
        a0 += v.y * w[2 * k + 2]; a1 += v.y * w[2 * k + 3];
        a0 += v.z * w[2 * k + 4]; a1 += v.z * w[2 * k + 5];
        a0 += v.w * w[2 * k + 6]; a1 += v.w * w[2 * k + 7];
    }
    out[(size_t)r * 2 + 0] = a0;
    out[(size_t)r * 2 + 1] = a1;
}

// ---------------- launch ------------------------------------------------------
extern "C" void kernel_launch(void* const* d_in, const int* in_sizes, int n_in,
                              void* d_out, int out_size)
{
    const bool setup_order = (in_sizes[5] == 2 * NEDGES);

    const float* des   = (const float*)d_in[0];
    const float* tweet = (const float*)d_in[1];
    const float* numf  = (const float*)d_in[2];
    const float* catf  = (const float*)d_in[3];
    const float* nf    = (const float*)d_in[4];
    const int* ei;
    const int* et;
    int wbase;
    if (setup_order) { ei = (const int*)d_in[5]; et = (const int*)d_in[6]; wbase = 7; }
    else             { ei = (const int*)d_in[27]; et = (const int*)d_in[28]; wbase = 5; }

#define WI(k) ((const float*)d_in[wbase + (k)])
    const float* W_des   = WI(0);  const float* b_des   = WI(1);
    const float* W_tweet = WI(2);  const float* b_tweet = WI(3);
    const float* W_num   = WI(4);  const float* b_num   = WI(5);
    const float* W_cat   = WI(6);  const float* b_cat   = WI(7);
    const float* W_new   = WI(8);  const float* b_new   = WI(9);
    const float* W_in    = WI(10); const float* b_in    = WI(11);
    const float* rel_w1  = WI(12); const float* root_w1 = WI(13); const float* bias1 = WI(14);
    const float* rel_w2  = WI(15); const float* root_w2 = WI(16); const float* bias2 = WI(17);
    const float* W_out1  = WI(18); const float* b_out1  = WI(19);
    const float* W_out2  = WI(20); const float* b_out2  = WI(21);
#undef WI

    float *x0, *x1, *x2, *x3, *xa, *wcat;
    cudaGetSymbolAddress((void**)&x0, g_x0);
    cudaGetSymbolAddress((void**)&x1, g_x1);
    cudaGetSymbolAddress((void**)&x2, g_x2);
    cudaGetSymbolAddress((void**)&x3, g_x3);
    cudaGetSymbolAddress((void**)&xa, g_xa);
    cudaGetSymbolAddress((void**)&wcat, g_wcat);

    const int MB = (NNODES + 127) / 128;  // 391

    // Feature transforms -> x0 [N,128]
    pad_w_kernel<<<(2 * 768 * 32 + 255) / 256, 256>>>(W_des, W_tweet);
    feat_small_kernel<<<(NNODES + 255) / 256, 256>>>(
        numf, catf, nf, W_num, b_num, W_cat, b_cat, W_new, b_new, x0);
    stream_gemm<<<dim3(MB, 2), 256>>>(des, tweet, b_des, b_tweet, x0);

    // x1 = lrelu(x0 @ W_in + b_in)
    gemm_kernel<64><<<dim3(MB, 2), 256>>>(x0, 128, W_in, 128, b_in,
                                          x1, 128, 0, NNODES, 128, 128, 1);

    // CSR by destination (shared by both RGCN layers)
    zero_cnt_kernel<<<(NNODES + 255) / 256, 256>>>();
    hist_kernel<<<(NEDGES + 255) / 256, 256>>>(ei);
    scan_kernel<<<1, 1024>>>();
    fill_kernel<<<(NEDGES + 255) / 256, 256>>>(ei, et);

    const int AGG_BLOCKS = (NNODES * 32 + 255) / 256;

    // RGCN layer 1
    build_wcat_kernel<<<192, 256>>>(rel_w1, root_w1);
    aggregate_kernel<<<AGG_BLOCKS, 256>>>(x1, xa);
    gemm_kernel<64><<<dim3(MB, 2), 256>>>(xa, 384, wcat, 128, bias1,
                                          x2, 128, 0, NNODES, 384, 128, 0);

    // RGCN layer 2
    build_wcat_kernel<<<192, 256>>>(rel_w2, root_w2);
    aggregate_kernel<<<AGG_BLOCKS, 256>>>(x2, xa);
    gemm_kernel<64><<<dim3(MB, 2), 256>>>(xa, 384, wcat, 128, bias2,
                                          x3, 128, 0, NNODES, 384, 128, 0);

    // Head
    gemm_kernel<64><<<dim3(MB, 2), 256>>>(x3, 128, W_out1, 128, b_out1,
                                          x1, 128, 0, NNODES, 128, 128, 1);
    final_kernel<<<(NNODES + 255) / 256, 256>>>(x1, W_out2, b_out2, (float*)d_out);
}

// round 5
// speedup vs baseline: 1.2691x; 1.0110x over previous
#include <cuda_runtime.h>
#include <stdint.h>

#define NNODES 50000
#define NEDGES 600000

// ---------------- scratch (static device globals; no dynamic alloc) ----------
__device__ float g_x0[(size_t)NNODES * 128];
__device__ float g_x1[(size_t)NNODES * 128];
__device__ float g_x2[(size_t)NNODES * 128];
__device__ float g_x3[(size_t)NNODES * 128];
__device__ float g_agg[(size_t)NNODES * 256];
__device__ float g_wcat1[384 * 128];
__device__ float g_wcat2[384 * 128];
__device__ float g_wpad[2 * 768 * 32];
__device__ int   g_cnt[NNODES];
__device__ int   g_rowptr[NNODES + 1];
__device__ int   g_cursor[NNODES];
__device__ int   g_adj[NEDGES];

// ---------------- helpers ----------------------------------------------------
typedef unsigned long long ull;

__device__ __forceinline__ float lrelu(float x) { return x > 0.f ? x : 0.01f * x; }

__device__ __forceinline__ void ffma2(ull& d, ull a, ull b, ull c) {
    asm("fma.rn.f32x2 %0, %1, %2, %3;" : "=l"(d) : "l"(a), "l"(b), "l"(c));
}
__device__ __forceinline__ ull dup2(float x) {
    ull r; asm("mov.b64 %0, {%1, %1};" : "=l"(r) : "f"(x)); return r;
}
__device__ __forceinline__ float2 unpk(ull v) {
    float2 r; asm("mov.b64 {%0, %1}, %2;" : "=f"(r.x), "=f"(r.y) : "l"(v)); return r;
}

__device__ __forceinline__ void cp_async16(uint32_t smem, const void* gptr, int bytes) {
    asm volatile("cp.async.cg.shared.global [%0], [%1], 16, %2;"
                 :: "r"(smem), "l"(gptr), "r"(bytes) : "memory");
}
__device__ __forceinline__ void cp_commit() {
    asm volatile("cp.async.commit_group;" ::: "memory");
}
template <int N>
__device__ __forceinline__ void cp_wait() {
    asm volatile("cp.async.wait_group %0;" :: "n"(N) : "memory");
}

// ---------------- streaming GEMM for des/tweet (K=768, NC<=32) ---------------
__global__ __launch_bounds__(256) void stream_gemm(
    const float* __restrict__ A0, const float* __restrict__ A1,
    const float* __restrict__ bias0, const float* __restrict__ bias1,
    float* __restrict__ C)
{
    constexpr int K = 768, BM = 128, BK = 32, LDA = 36;
    __shared__ float As[2][BM * LDA];
    __shared__ float Bs[2][BK * 32];

    const int y = blockIdx.y;
    const float* A    = y ? A1 : A0;
    const float* bias = y ? bias1 : bias0;
    const float* Wp   = g_wpad + y * (768 * 32);
    const int col_off = y ? 25 : 0;
    const int NC      = y ? 28 : 25;

    const int tid = threadIdx.x;
    const int tx = tid & 7;
    const int ty = tid >> 3;
    const int bm = blockIdx.x * BM;

    uint32_t as_u[2], bs_u[2];
    as_u[0] = (uint32_t)__cvta_generic_to_shared(&As[0][0]);
    as_u[1] = (uint32_t)__cvta_generic_to_shared(&As[1][0]);
    bs_u[0] = (uint32_t)__cvta_generic_to_shared(&Bs[0][0]);
    bs_u[1] = (uint32_t)__cvta_generic_to_shared(&Bs[1][0]);

    ull acc[4][2];
#pragma unroll
    for (int i = 0; i < 4; i++) { acc[i][0] = 0ull; acc[i][1] = 0ull; }

    auto stage = [&](int s, int k0) {
#pragma unroll
        for (int j = 0; j < 4; j++) {
            int unit = tid + j * 256;
            int row = unit >> 3;
            int seg = unit & 7;
            int gr = bm + row;
            cp_async16(as_u[s] + (uint32_t)(row * (LDA * 4) + seg * 16),
                       A + (size_t)gr * K + k0 + seg * 4,
                       gr < NNODES ? 16 : 0);
        }
        {
            int kr = tid >> 3;
            int seg = tid & 7;
            cp_async16(bs_u[s] + (uint32_t)(kr * 128 + seg * 16),
                       Wp + (size_t)(k0 + kr) * 32 + seg * 4, 16);
        }
    };

    stage(0, 0);
    cp_commit();

    for (int c = 0; c < K / BK; c++) {
        const int s = c & 1;
        if (c + 1 < K / BK) {
            stage(s ^ 1, (c + 1) * BK);
            cp_commit();
            cp_wait<1>();
        } else {
            cp_wait<0>();
        }
        __syncthreads();

        const float* as = &As[s][0];
        const float* bs = &Bs[s][0];
#pragma unroll
        for (int kk = 0; kk < BK; kk++) {
            ull b01 = *reinterpret_cast<const ull*>(bs + kk * 32 + tx * 4);
            ull b23 = *reinterpret_cast<const ull*>(bs + kk * 32 + tx * 4 + 2);
#pragma unroll
            for (int i = 0; i < 4; i++) {
                float a = as[(ty + 32 * i) * LDA + kk];
                ull a2 = dup2(a);
                ffma2(acc[i][0], a2, b01, acc[i][0]);
                ffma2(acc[i][1], a2, b23, acc[i][1]);
            }
        }
        __syncthreads();
    }

    float bv[4];
#pragma unroll
    for (int j = 0; j < 4; j++) {
        int gc = tx * 4 + j;
        bv[j] = (gc < NC) ? bias[gc] : 0.f;
    }
#pragma unroll
    for (int i = 0; i < 4; i++) {
        int row = bm + ty + 32 * i;
        if (row >= NNODES) continue;
        float2 v01 = unpk(acc[i][0]);
        float2 v23 = unpk(acc[i][1]);
        float o[4] = {v01.x, v01.y, v23.x, v23.y};
        float* cr = C + (size_t)row * 128 + col_off;
#pragma unroll
        for (int j = 0; j < 4; j++) {
            int gc = tx * 4 + j;
            if (gc < NC) cr[gc] = lrelu(o[j] + bv[j]);
        }
    }
}

// ---------------- prep: pad W, build both wcat, zero cnt ---------------------
__global__ void prep_kernel(const float* __restrict__ Wd,
                            const float* __restrict__ Wt,
                            const float* __restrict__ relw1,
                            const float* __restrict__ rootw1,
                            const float* __restrict__ relw2,
                            const float* __restrict__ rootw2) {
    int i = blockIdx.x * blockDim.x + threadIdx.x;
    // wpad: 2 * 768 * 32 = 49152
    if (i < 2 * 768 * 32) {
        int which = i >= 768 * 32;
        int r = i - which * 768 * 32;
        int k = r >> 5, j = r & 31;
        float v = 0.f;
        if (!which) { if (j < 25) v = Wd[k * 25 + j]; }
        else        { if (j < 28) v = Wt[k * 28 + j]; }
        g_wpad[i] = v;
    }
    // wcat1 / wcat2: 49152 each
    if (i < 49152) {
        g_wcat1[i] = (i < 32768) ? relw1[i] : rootw1[i - 32768];
        g_wcat2[i] = (i < 32768) ? relw2[i] : rootw2[i - 32768];
    }
    // zero cnt
    if (i < NNODES) g_cnt[i] = 0;
}

// ---------------- FFMA2 GEMM (generic, W_in / W_out1) ------------------------
template <int BN>
__global__ __launch_bounds__(256) void gemm_kernel(
    const float* __restrict__ A, int lda,
    const float* __restrict__ W, int ldw,
    const float* __restrict__ bias,
    float* __restrict__ C, int ldc, int col_off,
    int M, int K, int NC, int relu)
{
    constexpr int BM = 128, BK = 16;
    constexpr int NTX = BN / 4;
    constexpr int NTY = 256 / NTX;
    constexpr int TM  = BM / NTY;
    constexpr int NPAIR = TM / 2;

    __shared__ float As[BK][BM];
    __shared__ float Bs[BK][BN];

    const int tid = threadIdx.x;
    const int tx = tid % NTX, ty = tid / NTX;
    const int bm = blockIdx.x * BM;
    const int bn = blockIdx.y * BN;

    ull acc[NPAIR][4];
#pragma unroll
    for (int p = 0; p < NPAIR; p++)
#pragma unroll
        for (int j = 0; j < 4; j++) acc[p][j] = 0ull;

    for (int k0 = 0; k0 < K; k0 += BK) {
#pragma unroll
        for (int i = 0; i < 2; i++) {
            int idx = tid * 2 + i;
            int row = idx >> 2;
            int kq = (idx & 3) << 2;
            float4 v = make_float4(0.f, 0.f, 0.f, 0.f);
            int gr = bm + row;
            if (gr < M)
                v = *reinterpret_cast<const float4*>(A + (size_t)gr * lda + k0 + kq);
            As[kq + 0][row] = v.x;
            As[kq + 1][row] = v.y;
            As[kq + 2][row] = v.z;
            As[kq + 3][row] = v.w;
        }
        constexpr int EB = (BK * BN) / 256;
#pragma unroll
        for (int i = 0; i < EB; i++) {
            int idx = tid * EB + i;
            int krow = idx / BN;
            int col = idx % BN;
            int gc = bn + col;
            float v = 0.f;
            if (gc < NC) v = W[(size_t)(k0 + krow) * ldw + gc];
            Bs[krow][col] = v;
        }
        __syncthreads();

#pragma unroll
        for (int kk = 0; kk < BK; kk++) {
            const float* ap = &As[kk][ty * TM];
            ull a[NPAIR];
#pragma unroll
            for (int p = 0; p < NPAIR; p++)
                a[p] = *reinterpret_cast<const ull*>(ap + 2 * p);
            float4 bf = *reinterpret_cast<const float4*>(&Bs[kk][tx * 4]);
            ull b0 = dup2(bf.x), b1 = dup2(bf.y), b2 = dup2(bf.z), b3 = dup2(bf.w);
#pragma unroll
            for (int p = 0; p < NPAIR; p++) {
                ffma2(acc[p][0], a[p], b0, acc[p][0]);
                ffma2(acc[p][1], a[p], b1, acc[p][1]);
                ffma2(acc[p][2], a[p], b2, acc[p][2]);
                ffma2(acc[p][3], a[p], b3, acc[p][3]);
            }
        }
        __syncthreads();
    }

    float bv[4];
#pragma unroll
    for (int j = 0; j < 4; j++) {
        int gc = bn + tx * 4 + j;
        bv[j] = (gc < NC) ? bias[gc] : 0.f;
    }
#pragma unroll
    for (int p = 0; p < NPAIR; p++) {
#pragma unroll
        for (int j = 0; j < 4; j++) {
            int gc = bn + tx * 4 + j;
            if (gc < NC) {
                float2 v = unpk(acc[p][j]);
                float o0 = v.x + bv[j];
                float o1 = v.y + bv[j];
                if (relu) { o0 = lrelu(o0); o1 = lrelu(o1); }
                int r0 = bm + ty * TM + 2 * p;
                if (r0 < M)     C[(size_t)r0 * ldc + col_off + gc] = o0;
                if (r0 + 1 < M) C[(size_t)(r0 + 1) * ldc + col_off + gc] = o1;
            }
        }
    }
}

// ---------------- RGCN GEMM: C = [agg(256) | x(128)] @ wcat + bias -----------
// Same structure as gemm_kernel<64>, K fixed 384, A split across two arrays.
__global__ __launch_bounds__(256) void rgcn_gemm(
    const float* __restrict__ Agg,   // [N,256]
    const float* __restrict__ X,     // [N,128]
    const float* __restrict__ W,     // [384,128]
    const float* __restrict__ bias,  // [128]
    float* __restrict__ C)           // [N,128]
{
    constexpr int BM = 128, BK = 16, BN = 64;
    constexpr int NTX = 16, NTY = 16, TM = 8, NPAIR = 4;

    __shared__ float As[BK][BM];
    __shared__ float Bs[BK][BN];

    const int tid = threadIdx.x;
    const int tx = tid % NTX, ty = tid / NTX;
    const int bm = blockIdx.x * BM;
    const int bn = blockIdx.y * BN;

    ull acc[NPAIR][4];
#pragma unroll
    for (int p = 0; p < NPAIR; p++)
#pragma unroll
        for (int j = 0; j < 4; j++) acc[p][j] = 0ull;

    for (int k0 = 0; k0 < 384; k0 += BK) {
        const float* A = (k0 < 256) ? Agg : X;
        const int lda  = (k0 < 256) ? 256 : 128;
        const int kb   = (k0 < 256) ? k0 : (k0 - 256);
#pragma unroll
        for (int i = 0; i < 2; i++) {
            int idx = tid * 2 + i;
            int row = idx >> 2;
            int kq = (idx & 3) << 2;
            float4 v = make_float4(0.f, 0.f, 0.f, 0.f);
            int gr = bm + row;
            if (gr < NNODES)
                v = *reinterpret_cast<const float4*>(A + (size_t)gr * lda + kb + kq);
            As[kq + 0][row] = v.x;
            As[kq + 1][row] = v.y;
            As[kq + 2][row] = v.z;
            As[kq + 3][row] = v.w;
        }
#pragma unroll
        for (int i = 0; i < 4; i++) {
            int idx = tid * 4 + i;
            int krow = idx / BN;
            int col = idx % BN;
            Bs[krow][col] = W[(size_t)(k0 + krow) * 128 + bn + col];
        }
        __syncthreads();

#pragma unroll
        for (int kk = 0; kk < BK; kk++) {
            const float* ap = &As[kk][ty * TM];
            ull a[NPAIR];
#pragma unroll
            for (int p = 0; p < NPAIR; p++)
                a[p] = *reinterpret_cast<const ull*>(ap + 2 * p);
            float4 bf = *reinterpret_cast<const float4*>(&Bs[kk][tx * 4]);
            ull b0 = dup2(bf.x), b1 = dup2(bf.y), b2 = dup2(bf.z), b3 = dup2(bf.w);
#pragma unroll
            for (int p = 0; p < NPAIR; p++) {
                ffma2(acc[p][0], a[p], b0, acc[p][0]);
                ffma2(acc[p][1], a[p], b1, acc[p][1]);
                ffma2(acc[p][2], a[p], b2, acc[p][2]);
                ffma2(acc[p][3], a[p], b3, acc[p][3]);
            }
        }
        __syncthreads();
    }

    float bv[4];
#pragma unroll
    for (int j = 0; j < 4; j++) bv[j] = bias[bn + tx * 4 + j];
#pragma unroll
    for (int p = 0; p < NPAIR; p++) {
        int r0 = bm + ty * TM + 2 * p;
#pragma unroll
        for (int j = 0; j < 4; j++) {
            float2 v = unpk(acc[p][j]);
            int gc = bn + tx * 4 + j;
            if (r0 < NNODES)     C[(size_t)r0 * 128 + gc] = v.x + bv[j];
            if (r0 + 1 < NNODES) C[(size_t)(r0 + 1) * 128 + gc] = v.y + bv[j];
        }
    }
}

// ---------------- small-K feature columns (num/cat/new -> x0 cols 53..127) ---
__global__ void feat_small_kernel(
    const float* __restrict__ numf, const float* __restrict__ catf,
    const float* __restrict__ nf,
    const float* __restrict__ Wn, const float* __restrict__ bn,
    const float* __restrict__ Wc, const float* __restrict__ bc,
    const float* __restrict__ Ww, const float* __restrict__ bw,
    float* __restrict__ x0)
{
    __shared__ float sWn[7 * 25], sbn[25], sWc[11 * 25], sbc[25], sWw[25], sbw[25];
    int tid = threadIdx.x;
    for (int i = tid; i < 7 * 25; i += blockDim.x) sWn[i] = Wn[i];
    for (int i = tid; i < 11 * 25; i += blockDim.x) sWc[i] = Wc[i];
    for (int i = tid; i < 25; i += blockDim.x) {
        sbn[i] = bn[i]; sbc[i] = bc[i]; sWw[i] = Ww[i]; sbw[i] = bw[i];
    }
    __syncthreads();

    int r = blockIdx.x * blockDim.x + tid;
    if (r >= NNODES) return;

    float nv[7], cv[11];
#pragma unroll
    for (int k = 0; k < 7; k++) nv[k] = numf[(size_t)r * 7 + k];
#pragma unroll
    for (int k = 0; k < 11; k++) cv[k] = catf[(size_t)r * 11 + k];
    float wv = nf[r];

    float* out = x0 + (size_t)r * 128;
#pragma unroll
    for (int j = 0; j < 25; j++) {
        float a = sbn[j];
#pragma unroll
        for (int k = 0; k < 7; k++) a += nv[k] * sWn[k * 25 + j];
        out[53 + j] = lrelu(a);
    }
#pragma unroll
    for (int j = 0; j < 25; j++) {
        float a = sbc[j];
#pragma unroll
        for (int k = 0; k < 11; k++) a += cv[k] * sWc[k * 25 + j];
        out[78 + j] = lrelu(a);
    }
#pragma unroll
    for (int j = 0; j < 25; j++)
        out[103 + j] = lrelu(wv * sWw[j] + sbw[j]);
}

// ---------------- CSR build ---------------------------------------------------
__global__ void hist_kernel(const int* __restrict__ ei) {
    int e = blockIdx.x * blockDim.x + threadIdx.x;
    if (e < NEDGES) atomicAdd(&g_cnt[ei[NEDGES + e]], 1);
}

__global__ void scan_kernel() {
    __shared__ int wsum[32];
    __shared__ int carry;
    int tid = threadIdx.x, lane = tid & 31, wid = tid >> 5;
    if (tid == 0) carry = 0;
    __syncthreads();
    for (int base = 0; base < NNODES; base += 1024) {
        int i = base + tid;
        int v = (i < NNODES) ? g_cnt[i] : 0;
        int x = v;
#pragma unroll
        for (int o = 1; o < 32; o <<= 1) {
            int y = __shfl_up_sync(0xffffffffu, x, o);
            if (lane >= o) x += y;
        }
        if (lane == 31) wsum[wid] = x;
        __syncthreads();
        if (wid == 0) {
            int s = wsum[lane];
#pragma unroll
            for (int o = 1; o < 32; o <<= 1) {
                int y = __shfl_up_sync(0xffffffffu, s, o);
                if (lane >= o) s += y;
            }
            wsum[lane] = s;
        }
        __syncthreads();
        int c = carry;
        int woff = wid ? wsum[wid - 1] : 0;
        int excl = c + woff + x - v;
        if (i < NNODES) { g_rowptr[i] = excl; g_cursor[i] = excl; }
        int total = wsum[31];
        __syncthreads();
        if (tid == 0) carry = c + total;
        __syncthreads();
    }
    if (threadIdx.x == 0) g_rowptr[NNODES] = NEDGES;
}

__global__ void fill_kernel(const int* __restrict__ ei, const int* __restrict__ et) {
    int e = blockIdx.x * blockDim.x + threadIdx.x;
    if (e < NEDGES) {
        int s = ei[e];
        int d = ei[NEDGES + e];
        int t = et[e];
        int p = atomicAdd(&g_cursor[d], 1);
        g_adj[p] = s | (t << 30);
    }
}

// ---------------- aggregation: agg = [sumA/deg | sumB/deg]  [N,256] ----------
// Warp per node. Adjacency prefetched 32-wide per lane, broadcast via shfl;
// x-row loads batched 4x for MLP.
__global__ __launch_bounds__(256) void aggregate_kernel(
    const float* __restrict__ xin, float* __restrict__ agg)
{
    const int w = (blockIdx.x * blockDim.x + threadIdx.x) >> 5;
    const int lane = threadIdx.x & 31;
    if (w >= NNODES) return;
    const int beg = g_rowptr[w], end = g_rowptr[w + 1];
    const int deg = end - beg;

    float4 aA = make_float4(0.f, 0.f, 0.f, 0.f);
    float4 aB = make_float4(0.f, 0.f, 0.f, 0.f);

    for (int t0 = 0; t0 < deg; t0 += 32) {
        int e = beg + t0 + lane;
        int pk = (e < end) ? g_adj[e] : 0;
        int nv = min(deg - t0, 32);
        int j = 0;
        for (; j + 4 <= nv; j += 4) {
            int p0 = __shfl_sync(0xffffffffu, pk, j);
            int p1 = __shfl_sync(0xffffffffu, pk, j + 1);
            int p2 = __shfl_sync(0xffffffffu, pk, j + 2);
            int p3 = __shfl_sync(0xffffffffu, pk, j + 3);
            float4 v0 = *reinterpret_cast<const float4*>(
                xin + (size_t)(p0 & 0x3FFFFFFF) * 128 + lane * 4);
            float4 v1 = *reinterpret_cast<const float4*>(
                xin + (size_t)(p1 & 0x3FFFFFFF) * 128 + lane * 4);
            float4 v2 = *reinterpret_cast<const float4*>(
                xin + (size_t)(p2 & 0x3FFFFFFF) * 128 + lane * 4);
            float4 v3 = *reinterpret_cast<const float4*>(
                xin + (size_t)(p3 & 0x3FFFFFFF) * 128 + lane * 4);
            if (p0 >> 30) { aB.x += v0.x; aB.y += v0.y; aB.z += v0.z; aB.w += v0.w; }
            else          { aA.x += v0.x; aA.y += v0.y; aA.z += v0.z; aA.w += v0.w; }
            if (p1 >> 30) { aB.x += v1.x; aB.y += v1.y; aB.z += v1.z; aB.w += v1.w; }
            else          { aA.x += v1.x; aA.y += v1.y; aA.z += v1.z; aA.w += v1.w; }
            if (p2 >> 30) { aB.x += v2.x; aB.y += v2.y; aB.z += v2.z; aB.w += v2.w; }
            else          { aA.x += v2.x; aA.y += v2.y; aA.z += v2.z; aA.w += v2.w; }
            if (p3 >> 30) { aB.x += v3.x; aB.y += v3.y; aB.z += v3.z; aB.w += v3.w; }
            else          { aA.x += v3.x; aA.y += v3.y; aA.z += v3.z; aA.w += v3.w; }
        }
        for (; j < nv; j++) {
            int p = __shfl_sync(0xffffffffu, pk, j);
            float4 v = *reinterpret_cast<const float4*>(
                xin + (size_t)(p & 0x3FFFFFFF) * 128 + lane * 4);
            if (p >> 30) { aB.x += v.x; aB.y += v.y; aB.z += v.z; aB.w += v.w; }
            else         { aA.x += v.x; aA.y += v.y; aA.z += v.z; aA.w += v.w; }
        }
    }

    const float s = 1.f / (float)(deg > 0 ? deg : 1);
    float* o = agg + (size_t)w * 256 + lane * 4;
    *reinterpret_cast<float4*>(o) =
        make_float4(aA.x * s, aA.y * s, aA.z * s, aA.w * s);
    *reinterpret_cast<float4*>(o + 128) =
        make_float4(aB.x * s, aB.y * s, aB.z * s, aB.w * s);
}

// ---------------- final: out = x @ W_out2 + b_out2 (N x 2) -------------------
__global__ void final_kernel(const float* __restrict__ x,
                             const float* __restrict__ W,
                             const float* __restrict__ b,
                             float* __restrict__ out) {
    __shared__ float w[256];
    __shared__ float bb[2];
    int tid = threadIdx.x;
    for (int i = tid; i < 256; i += blockDim.x) w[i] = W[i];
    if (tid < 2) bb[tid] = b[tid];
    __syncthreads();
    int r = blockIdx.x * blockDim.x + tid;
    if (r >= NNODES) return;
    float a0 = bb[0], a1 = bb[1];
    const float4* xr = reinterpret_cast<const float4*>(x + (size_t)r * 128);
#pragma unroll
    for (int k4 = 0; k4 < 32; k4++) {
        float4 v = xr[k4];
        int k = k4 * 4;
        a0 += v.x * w[2 * k + 0]; a1 += v.x * w[2 * k + 1];
        a0 += v.y * w[2 * k + 2]; a1 += v.y * w[2 * k + 3];
        a0 += v.z * w[2 * k + 4]; a1 += v.z * w[2 * k + 5];
        a0 += v.w * w[2 * k + 6]; a1 += v.w * w[2 * k + 7];
    }
    out[(size_t)r * 2 + 0] = a0;
    out[(size_t)r * 2 + 1] = a1;
}

// ---------------- launch ------------------------------------------------------
extern "C" void kernel_launch(void* const* d_in, const int* in_sizes, int n_in,
                              void* d_out, int out_size)
{
    const bool setup_order = (in_sizes[5] == 2 * NEDGES);

    const float* des   = (const float*)d_in[0];
    const float* tweet = (const float*)d_in[1];
    const float* numf  = (const float*)d_in[2];
    const float* catf  = (const float*)d_in[3];
    const float* nf    = (const float*)d_in[4];
    const int* ei;
    const int* et;
    int wbase;
    if (setup_order) { ei = (const int*)d_in[5]; et = (const int*)d_in[6]; wbase = 7; }
    else             { ei = (const int*)d_in[27]; et = (const int*)d_in[28]; wbase = 5; }

#define WI(k) ((const float*)d_in[wbase + (k)])
    const float* W_des   = WI(0);  const float* b_des   = WI(1);
    const float* W_tweet = WI(2);  const float* b_tweet = WI(3);
    const float* W_num   = WI(4);  const float* b_num   = WI(5);
    const float* W_cat   = WI(6);  const float* b_cat   = WI(7);
    const float* W_new   = WI(8);  const float* b_new   = WI(9);
    const float* W_in    = WI(10); const float* b_in    = WI(11);
    const float* rel_w1  = WI(12); const float* root_w1 = WI(13); const float* bias1 = WI(14);
    const float* rel_w2  = WI(15); const float* root_w2 = WI(16); const float* bias2 = WI(17);
    const float* W_out1  = WI(18); const float* b_out1  = WI(19);
    const float* W_out2  = WI(20); const float* b_out2  = WI(21);
#undef WI

    float *x0, *x1, *x2, *x3, *agg, *wcat1, *wcat2;
    cudaGetSymbolAddress((void**)&x0, g_x0);
    cudaGetSymbolAddress((void**)&x1, g_x1);
    cudaGetSymbolAddress((void**)&x2, g_x2);
    cudaGetSymbolAddress((void**)&x3, g_x3);
    cudaGetSymbolAddress((void**)&agg, g_agg);
    cudaGetSymbolAddress((void**)&wcat1, g_wcat1);
    cudaGetSymbolAddress((void**)&wcat2, g_wcat2);

    const int MB = (NNODES + 127) / 128;  // 391

    // Prep (wpad, both wcats, zero cnt) + CSR build
    prep_kernel<<<(NNODES + 255) / 256, 256>>>(W_des, W_tweet,
                                               rel_w1, root_w1, rel_w2, root_w2);
    hist_kernel<<<(NEDGES + 255) / 256, 256>>>(ei);
    scan_kernel<<<1, 1024>>>();
    fill_kernel<<<(NEDGES + 255) / 256, 256>>>(ei, et);

    // Feature transforms -> x0 [N,128]
    feat_small_kernel<<<(NNODES + 255) / 256, 256>>>(
        numf, catf, nf, W_num, b_num, W_cat, b_cat, W_new, b_new, x0);
    stream_gemm<<<dim3(MB, 2), 256>>>(des, tweet, b_des, b_tweet, x0);

    // x1 = lrelu(x0 @ W_in + b_in)
    gemm_kernel<64><<<dim3(MB, 2), 256>>>(x0, 128, W_in, 128, b_in,
                                          x1, 128, 0, NNODES, 128, 128, 1);

    const int AGG_BLOCKS = (NNODES + 7) / 8;  // warp per node, 8 warps/block

    // RGCN layer 1
    aggregate_kernel<<<AGG_BLOCKS, 256>>>(x1, agg);
    rgcn_gemm<<<dim3(MB, 2), 256>>>(agg, x1, wcat1, bias1, x2);

    // RGCN layer 2
    aggregate_kernel<<<AGG_BLOCKS, 256>>>(x2, agg);
    rgcn_gemm<<<dim3(MB, 2), 256>>>(agg, x2, wcat2, bias2, x3);

    // Head
    gemm_kernel<64><<<dim3(MB, 2), 256>>>(x3, 128, W_out1, 128, b_out1,
                                          x1, 128, 0, NNODES, 128, 128, 1);
    final_kernel<<<(NNODES + 255) / 256, 256>>>(x1, W_out2, b_out2, (float*)d_out);
}

// round 6
// speedup vs baseline: 1.4062x; 1.1080x over previous
#include <cuda_runtime.h>
#include <stdint.h>

#define NNODES 50000
#define NEDGES 600000

// ---------------- scratch (static device globals; no dynamic alloc) ----------
__device__ float g_x0[(size_t)NNODES * 128];
__device__ float g_x1[(size_t)NNODES * 128];
__device__ float g_x2[(size_t)NNODES * 128];
__device__ float g_x3[(size_t)NNODES * 128];
__device__ float g_agg[(size_t)NNODES * 256];
__device__ float g_wcat1[384 * 128];
__device__ float g_wcat2[384 * 128];
__device__ float g_wpad[2 * 768 * 32];
__device__ int   g_cnt[NNODES];
__device__ int   g_rowptr[NNODES + 1];
__device__ int   g_cursor[NNODES];
__device__ int   g_adj[NEDGES];

// ---------------- helpers ----------------------------------------------------
typedef unsigned long long ull;

__device__ __forceinline__ float lrelu(float x) { return x > 0.f ? x : 0.01f * x; }

__device__ __forceinline__ void ffma2(ull& d, ull a, ull b, ull c) {
    asm("fma.rn.f32x2 %0, %1, %2, %3;" : "=l"(d) : "l"(a), "l"(b), "l"(c));
}
__device__ __forceinline__ ull dup2(float x) {
    ull r; asm("mov.b64 %0, {%1, %1};" : "=l"(r) : "f"(x)); return r;
}
__device__ __forceinline__ float2 unpk(ull v) {
    float2 r; asm("mov.b64 {%0, %1}, %2;" : "=f"(r.x), "=f"(r.y) : "l"(v)); return r;
}

__device__ __forceinline__ void cp_async16(uint32_t smem, const void* gptr, int bytes) {
    asm volatile("cp.async.cg.shared.global [%0], [%1], 16, %2;"
                 :: "r"(smem), "l"(gptr), "r"(bytes) : "memory");
}
__device__ __forceinline__ void cp_commit() {
    asm volatile("cp.async.commit_group;" ::: "memory");
}
template <int N>
__device__ __forceinline__ void cp_wait() {
    asm volatile("cp.async.wait_group %0;" :: "n"(N) : "memory");
}

// ---------------- unified pipelined GEMM: C[N,128] = act(A[N,K] @ W[K,128]+b)
// A may be split: k < ksplit from A1 (lda1), else A2 (lda2, offset k-ksplit).
// BM=128, BN=64 (grid.y=2), BK=16, 256 threads, 2-stage cp.async pipeline.
__global__ __launch_bounds__(256) void pipe_gemm(
    const float* __restrict__ A1, int lda1, int ksplit,
    const float* __restrict__ A2, int lda2,
    const float* __restrict__ W,          // [K,128] row-major
    const float* __restrict__ bias,       // [128]
    float* __restrict__ C,                // [N,128]
    int K, int relu)
{
    constexpr int LDA = 20;   // padded row stride in floats (80B)
    __shared__ float As[2][128 * LDA];
    __shared__ float Bs[2][16 * 64];

    const int tid = threadIdx.x;
    const int tx = tid & 15;          // 16 col groups (4 cols each)
    const int ty = tid >> 4;          // 16 row groups (8 rows each)
    const int bm = blockIdx.x * 128;
    const int bn = blockIdx.y * 64;

    uint32_t asu[2], bsu[2];
    asu[0] = (uint32_t)__cvta_generic_to_shared(&As[0][0]);
    asu[1] = (uint32_t)__cvta_generic_to_shared(&As[1][0]);
    bsu[0] = (uint32_t)__cvta_generic_to_shared(&Bs[0][0]);
    bsu[1] = (uint32_t)__cvta_generic_to_shared(&Bs[1][0]);

    ull acc[8][2];
#pragma unroll
    for (int r = 0; r < 8; r++) { acc[r][0] = 0ull; acc[r][1] = 0ull; }

    auto stage = [&](int s, int k0) {
        const float* A; int lda, kb;
        if (k0 < ksplit) { A = A1; lda = lda1; kb = k0; }
        else             { A = A2; lda = lda2; kb = k0 - ksplit; }
        // A tile: 128 rows x 16 floats = 512 16B units
#pragma unroll
        for (int j = 0; j < 2; j++) {
            int unit = tid + j * 256;
            int row = unit >> 2;
            int u = unit & 3;
            int gr = bm + row;
            cp_async16(asu[s] + (uint32_t)(row * (LDA * 4) + u * 16),
                       A + (size_t)gr * lda + kb + u * 4,
                       gr < NNODES ? 16 : 0);
        }
        // B tile: 16 k-rows x 64 floats = 256 16B units
        {
            int kr = tid >> 4;
            int u = tid & 15;
            cp_async16(bsu[s] + (uint32_t)(kr * 256 + u * 16),
                       W + (size_t)(k0 + kr) * 128 + bn + u * 4, 16);
        }
    };

    stage(0, 0);
    cp_commit();

    const int NCH = K / 16;
    for (int c = 0; c < NCH; c++) {
        const int s = c & 1;
        if (c + 1 < NCH) {
            stage(s ^ 1, (c + 1) * 16);
            cp_commit();
            cp_wait<1>();
        } else {
            cp_wait<0>();
        }
        __syncthreads();

        const float* as = &As[s][(ty * 8) * LDA];
        const float* bs = &Bs[s][0];
#pragma unroll
        for (int kk = 0; kk < 16; kk++) {
            ull b0 = *reinterpret_cast<const ull*>(bs + kk * 64 + tx * 4);
            ull b1 = *reinterpret_cast<const ull*>(bs + kk * 64 + tx * 4 + 2);
#pragma unroll
            for (int r = 0; r < 8; r++) {
                ull a2 = dup2(as[r * LDA + kk]);
                ffma2(acc[r][0], a2, b0, acc[r][0]);
                ffma2(acc[r][1], a2, b1, acc[r][1]);
            }
        }
        __syncthreads();
    }

    // epilogue: bias (+lrelu) -> C
    const int col = bn + tx * 4;
    const float bv0 = bias[col + 0];
    const float bv1 = bias[col + 1];
    const float bv2 = bias[col + 2];
    const float bv3 = bias[col + 3];
#pragma unroll
    for (int r = 0; r < 8; r++) {
        int row = bm + ty * 8 + r;
        if (row >= NNODES) continue;
        float2 v0 = unpk(acc[r][0]);
        float2 v1 = unpk(acc[r][1]);
        float4 o;
        o.x = v0.x + bv0; o.y = v0.y + bv1;
        o.z = v1.x + bv2; o.w = v1.y + bv3;
        if (relu) { o.x = lrelu(o.x); o.y = lrelu(o.y); o.z = lrelu(o.z); o.w = lrelu(o.w); }
        *reinterpret_cast<float4*>(C + (size_t)row * 128 + col) = o;
    }
}

// ---------------- streaming GEMM for des/tweet (K=768, NC<=32) ---------------
__global__ __launch_bounds__(256) void stream_gemm(
    const float* __restrict__ A0, const float* __restrict__ A1,
    const float* __restrict__ bias0, const float* __restrict__ bias1,
    float* __restrict__ C)
{
    constexpr int K = 768, BM = 128, BK = 32, LDA = 36;
    __shared__ float As[2][BM * LDA];
    __shared__ float Bs[2][BK * 32];

    const int y = blockIdx.y;
    const float* A    = y ? A1 : A0;
    const float* bias = y ? bias1 : bias0;
    const float* Wp   = g_wpad + y * (768 * 32);
    const int col_off = y ? 25 : 0;
    const int NC      = y ? 28 : 25;

    const int tid = threadIdx.x;
    const int tx = tid & 7;
    const int ty = tid >> 3;
    const int bm = blockIdx.x * BM;

    uint32_t as_u[2], bs_u[2];
    as_u[0] = (uint32_t)__cvta_generic_to_shared(&As[0][0]);
    as_u[1] = (uint32_t)__cvta_generic_to_shared(&As[1][0]);
    bs_u[0] = (uint32_t)__cvta_generic_to_shared(&Bs[0][0]);
    bs_u[1] = (uint32_t)__cvta_generic_to_shared(&Bs[1][0]);

    ull acc[4][2];
#pragma unroll
    for (int i = 0; i < 4; i++) { acc[i][0] = 0ull; acc[i][1] = 0ull; }

    auto stage = [&](int s, int k0) {
#pragma unroll
        for (int j = 0; j < 4; j++) {
            int unit = tid + j * 256;
            int row = unit >> 3;
            int seg = unit & 7;
            int gr = bm + row;
            cp_async16(as_u[s] + (uint32_t)(row * (LDA * 4) + seg * 16),
                       A + (size_t)gr * K + k0 + seg * 4,
                       gr < NNODES ? 16 : 0);
        }
        {
            int kr = tid >> 3;
            int seg = tid & 7;
            cp_async16(bs_u[s] + (uint32_t)(kr * 128 + seg * 16),
                       Wp + (size_t)(k0 + kr) * 32 + seg * 4, 16);
        }
    };

    stage(0, 0);
    cp_commit();

    for (int c = 0; c < K / BK; c++) {
        const int s = c & 1;
        if (c + 1 < K / BK) {
            stage(s ^ 1, (c + 1) * BK);
            cp_commit();
            cp_wait<1>();
        } else {
            cp_wait<0>();
        }
        __syncthreads();

        const float* as = &As[s][0];
        const float* bs = &Bs[s][0];
#pragma unroll
        for (int kk = 0; kk < BK; kk++) {
            ull b01 = *reinterpret_cast<const ull*>(bs + kk * 32 + tx * 4);
            ull b23 = *reinterpret_cast<const ull*>(bs + kk * 32 + tx * 4 + 2);
#pragma unroll
            for (int i = 0; i < 4; i++) {
                float a = as[(ty + 32 * i) * LDA + kk];
                ull a2 = dup2(a);
                ffma2(acc[i][0], a2, b01, acc[i][0]);
                ffma2(acc[i][1], a2, b23, acc[i][1]);
            }
        }
        __syncthreads();
    }

    float bv[4];
#pragma unroll
    for (int j = 0; j < 4; j++) {
        int gc = tx * 4 + j;
        bv[j] = (gc < NC) ? bias[gc] : 0.f;
    }
#pragma unroll
    for (int i = 0; i < 4; i++) {
        int row = bm + ty + 32 * i;
        if (row >= NNODES) continue;
        float2 v01 = unpk(acc[i][0]);
        float2 v23 = unpk(acc[i][1]);
        float o[4] = {v01.x, v01.y, v23.x, v23.y};
        float* cr = C + (size_t)row * 128 + col_off;
#pragma unroll
        for (int j = 0; j < 4; j++) {
            int gc = tx * 4 + j;
            if (gc < NC) cr[gc] = lrelu(o[j] + bv[j]);
        }
    }
}

// ---------------- prep: pad W, build both wcat, zero cnt ---------------------
__global__ void prep_kernel(const float* __restrict__ Wd,
                            const float* __restrict__ Wt,
                            const float* __restrict__ relw1,
                            const float* __restrict__ rootw1,
                            const float* __restrict__ relw2,
                            const float* __restrict__ rootw2) {
    int i = blockIdx.x * blockDim.x + threadIdx.x;
    if (i < 2 * 768 * 32) {
        int which = i >= 768 * 32;
        int r = i - which * 768 * 32;
        int k = r >> 5, j = r & 31;
        float v = 0.f;
        if (!which) { if (j < 25) v = Wd[k * 25 + j]; }
        else        { if (j < 28) v = Wt[k * 28 + j]; }
        g_wpad[i] = v;
    }
    if (i < 49152) {
        g_wcat1[i] = (i < 32768) ? relw1[i] : rootw1[i - 32768];
        g_wcat2[i] = (i < 32768) ? relw2[i] : rootw2[i - 32768];
    }
    if (i < NNODES) g_cnt[i] = 0;
}

// ---------------- small-K feature columns (num/cat/new -> x0 cols 53..127) ---
__global__ void feat_small_kernel(
    const float* __restrict__ numf, const float* __restrict__ catf,
    const float* __restrict__ nf,
    const float* __restrict__ Wn, const float* __restrict__ bn,
    const float* __restrict__ Wc, const float* __restrict__ bc,
    const float* __restrict__ Ww, const float* __restrict__ bw,
    float* __restrict__ x0)
{
    __shared__ float sWn[7 * 25], sbn[25], sWc[11 * 25], sbc[25], sWw[25], sbw[25];
    int tid = threadIdx.x;
    for (int i = tid; i < 7 * 25; i += blockDim.x) sWn[i] = Wn[i];
    for (int i = tid; i < 11 * 25; i += blockDim.x) sWc[i] = Wc[i];
    for (int i = tid; i < 25; i += blockDim.x) {
        sbn[i] = bn[i]; sbc[i] = bc[i]; sWw[i] = Ww[i]; sbw[i] = bw[i];
    }
    __syncthreads();

    int r = blockIdx.x * blockDim.x + tid;
    if (r >= NNODES) return;

    float nv[7], cv[11];
#pragma unroll
    for (int k = 0; k < 7; k++) nv[k] = numf[(size_t)r * 7 + k];
#pragma unroll
    for (int k = 0; k < 11; k++) cv[k] = catf[(size_t)r * 11 + k];
    float wv = nf[r];

    float* out = x0 + (size_t)r * 128;
#pragma unroll
    for (int j = 0; j < 25; j++) {
        float a = sbn[j];
#pragma unroll
        for (int k = 0; k < 7; k++) a += nv[k] * sWn[k * 25 + j];
        out[53 + j] = lrelu(a);
    }
#pragma unroll
    for (int j = 0; j < 25; j++) {
        float a = sbc[j];
#pragma unroll
        for (int k = 0; k < 11; k++) a += cv[k] * sWc[k * 25 + j];
        out[78 + j] = lrelu(a);
    }
#pragma unroll
    for (int j = 0; j < 25; j++)
        out[103 + j] = lrelu(wv * sWw[j] + sbw[j]);
}

// ---------------- CSR build ---------------------------------------------------
__global__ void hist_kernel(const int* __restrict__ ei) {
    int e = blockIdx.x * blockDim.x + threadIdx.x;
    if (e < NEDGES) atomicAdd(&g_cnt[ei[NEDGES + e]], 1);
}

__global__ void scan_kernel() {
    __shared__ int wsum[32];
    __shared__ int carry;
    int tid = threadIdx.x, lane = tid & 31, wid = tid >> 5;
    if (tid == 0) carry = 0;
    __syncthreads();
    for (int base = 0; base < NNODES; base += 1024) {
        int i = base + tid;
        int v = (i < NNODES) ? g_cnt[i] : 0;
        int x = v;
#pragma unroll
        for (int o = 1; o < 32; o <<= 1) {
            int y = __shfl_up_sync(0xffffffffu, x, o);
            if (lane >= o) x += y;
        }
        if (lane == 31) wsum[wid] = x;
        __syncthreads();
        if (wid == 0) {
            int s = wsum[lane];
#pragma unroll
            for (int o = 1; o < 32; o <<= 1) {
                int y = __shfl_up_sync(0xffffffffu, s, o);
                if (lane >= o) s += y;
            }
            wsum[lane] = s;
        }
        __syncthreads();
        int c = carry;
        int woff = wid ? wsum[wid - 1] : 0;
        int excl = c + woff + x - v;
        if (i < NNODES) { g_rowptr[i] = excl; g_cursor[i] = excl; }
        int total = wsum[31];
        __syncthreads();
        if (tid == 0) carry = c + total;
        __syncthreads();
    }
    if (threadIdx.x == 0) g_rowptr[NNODES] = NEDGES;
}

__global__ void fill_kernel(const int* __restrict__ ei, const int* __restrict__ et) {
    int e = blockIdx.x * blockDim.x + threadIdx.x;
    if (e < NEDGES) {
        int s = ei[e];
        int d = ei[NEDGES + e];
        int t = et[e];
        int p = atomicAdd(&g_cursor[d], 1);
        g_adj[p] = s | (t << 30);
    }
}

// ---------------- aggregation: agg = [sumA/deg | sumB/deg]  [N,256] ----------
__global__ __launch_bounds__(256) void aggregate_kernel(
    const float* __restrict__ xin, float* __restrict__ agg)
{
    const int w = (blockIdx.x * blockDim.x + threadIdx.x) >> 5;
    const int lane = threadIdx.x & 31;
    if (w >= NNODES) return;
    const int beg = g_rowptr[w], end = g_rowptr[w + 1];
    const int deg = end - beg;

    float4 aA = make_float4(0.f, 0.f, 0.f, 0.f);
    float4 aB = make_float4(0.f, 0.f, 0.f, 0.f);

    for (int t0 = 0; t0 < deg; t0 += 32) {
        int e = beg + t0 + lane;
        int pk = (e < end) ? g_adj[e] : 0;
        int nv = min(deg - t0, 32);
        int j = 0;
        for (; j + 4 <= nv; j += 4) {
            int p0 = __shfl_sync(0xffffffffu, pk, j);
            int p1 = __shfl_sync(0xffffffffu, pk, j + 1);
            int p2 = __shfl_sync(0xffffffffu, pk, j + 2);
            int p3 = __shfl_sync(0xffffffffu, pk, j + 3);
            float4 v0 = *reinterpret_cast<const float4*>(
                xin + (size_t)(p0 & 0x3FFFFFFF) * 128 + lane * 4);
            float4 v1 = *reinterpret_cast<const float4*>(
                xin + (size_t)(p1 & 0x3FFFFFFF) * 128 + lane * 4);
            float4 v2 = *reinterpret_cast<const float4*>(
                xin + (size_t)(p2 & 0x3FFFFFFF) * 128 + lane * 4);
            float4 v3 = *reinterpret_cast<const float4*>(
                xin + (size_t)(p3 & 0x3FFFFFFF) * 128 + lane * 4);
            if (p0 >> 30) { aB.x += v0.x; aB.y += v0.y; aB.z += v0.z; aB.w += v0.w; }
            else          { aA.x += v0.x; aA.y += v0.y; aA.z += v0.z; aA.w += v0.w; }
            if (p1 >> 30) { aB.x += v1.x; aB.y += v1.y; aB.z += v1.z; aB.w += v1.w; }
            else          { aA.x += v1.x; aA.y += v1.y; aA.z += v1.z; aA.w += v1.w; }
            if (p2 >> 30) { aB.x += v2.x; aB.y += v2.y; aB.z += v2.z; aB.w += v2.w; }
            else          { aA.x += v2.x; aA.y += v2.y; aA.z += v2.z; aA.w += v2.w; }
            if (p3 >> 30) { aB.x += v3.x; aB.y += v3.y; aB.z += v3.z; aB.w += v3.w; }
            else          { aA.x += v3.x; aA.y += v3.y; aA.z += v3.z; aA.w += v3.w; }
        }
        for (; j < nv; j++) {
            int p = __shfl_sync(0xffffffffu, pk, j);
            float4 v = *reinterpret_cast<const float4*>(
                xin + (size_t)(p & 0x3FFFFFFF) * 128 + lane * 4);
            if (p >> 30) { aB.x += v.x; aB.y += v.y; aB.z += v.z; aB.w += v.w; }
            else         { aA.x += v.x; aA.y += v.y; aA.z += v.z; aA.w += v.w; }
        }
    }

    const float s = 1.f / (float)(deg > 0 ? deg : 1);
    float* o = agg + (size_t)w * 256 + lane * 4;
    *reinterpret_cast<float4*>(o) =
        make_float4(aA.x * s, aA.y * s, aA.z * s, aA.w * s);
    *reinterpret_cast<float4*>(o + 128) =
        make_float4(aB.x * s, aB.y * s, aB.z * s, aB.w * s);
}

// ---------------- final: out = x @ W_out2 + b_out2 (N x 2) -------------------
__global__ void final_kernel(const float* __restrict__ x,
                             const float* __restrict__ W,
                             const float* __restrict__ b,
                             float* __restrict__ out) {
    __shared__ float w[256];
    __shared__ float bb[2];
    int tid = threadIdx.x;
    for (int i = tid; i < 256; i += blockDim.x) w[i] = W[i];
    if (tid < 2) bb[tid] = b[tid];
    __syncthreads();
    int r = blockIdx.x * blockDim.x + tid;
    if (r >= NNODES) return;
    float a0 = bb[0], a1 = bb[1];
    const float4* xr = reinterpret_cast<const float4*>(x + (size_t)r * 128);
#pragma unroll
    for (int k4 = 0; k4 < 32; k4++) {
        float4 v = xr[k4];
        int k = k4 * 4;
        a0 += v.x * w[2 * k + 0]; a1 += v.x * w[2 * k + 1];
        a0 += v.y * w[2 * k + 2]; a1 += v.y * w[2 * k + 3];
        a0 += v.z * w[2 * k + 4]; a1 += v.z * w[2 * k + 5];
        a0 += v.w * w[2 * k + 6]; a1 += v.w * w[2 * k + 7];
    }
    out[(size_t)r * 2 + 0] = a0;
    out[(size_t)r * 2 + 1] = a1;
}

// ---------------- launch ------------------------------------------------------
extern "C" void kernel_launch(void* const* d_in, const int* in_sizes, int n_in,
                              void* d_out, int out_size)
{
    const bool setup_order = (in_sizes[5] == 2 * NEDGES);

    const float* des   = (const float*)d_in[0];
    const float* tweet = (const float*)d_in[1];
    const float* numf  = (const float*)d_in[2];
    const float* catf  = (const float*)d_in[3];
    const float* nf    = (const float*)d_in[4];
    const int* ei;
    const int* et;
    int wbase;
    if (setup_order) { ei = (const int*)d_in[5]; et = (const int*)d_in[6]; wbase = 7; }
    else             { ei = (const int*)d_in[27]; et = (const int*)d_in[28]; wbase = 5; }

#define WI(k) ((const float*)d_in[wbase + (k)])
    const float* W_des   = WI(0);  const float* b_des   = WI(1);
    const float* W_tweet = WI(2);  const float* b_tweet = WI(3);
    const float* W_num   = WI(4);  const float* b_num   = WI(5);
    const float* W_cat   = WI(6);  const float* b_cat   = WI(7);
    const float* W_new   = WI(8);  const float* b_new   = WI(9);
    const float* W_in    = WI(10); const float* b_in    = WI(11);
    const float* rel_w1  = WI(12); const float* root_w1 = WI(13); const float* bias1 = WI(14);
    const float* rel_w2  = WI(15); const float* root_w2 = WI(16); const float* bias2 = WI(17);
    const float* W_out1  = WI(18); const float* b_out1  = WI(19);
    const float* W_out2  = WI(20); const float* b_out2  = WI(21);
#undef WI

    float *x0, *x1, *x2, *x3, *agg, *wcat1, *wcat2;
    cudaGetSymbolAddress((void**)&x0, g_x0);
    cudaGetSymbolAddress((void**)&x1, g_x1);
    cudaGetSymbolAddress((void**)&x2, g_x2);
    cudaGetSymbolAddress((void**)&x3, g_x3);
    cudaGetSymbolAddress((void**)&agg, g_agg);
    cudaGetSymbolAddress((void**)&wcat1, g_wcat1);
    cudaGetSymbolAddress((void**)&wcat2, g_wcat2);

    const int MB = (NNODES + 127) / 128;  // 391

    // Prep + CSR build
    prep_kernel<<<(NNODES + 255) / 256, 256>>>(W_des, W_tweet,
                                               rel_w1, root_w1, rel_w2, root_w2);
    hist_kernel<<<(NEDGES + 255) / 256, 256>>>(ei);
    scan_kernel<<<1, 1024>>>();
    fill_kernel<<<(NEDGES + 255) / 256, 256>>>(ei, et);

    // Feature transforms -> x0 [N,128]
    feat_small_kernel<<<(NNODES + 255) / 256, 256>>>(
        numf, catf, nf, W_num, b_num, W_cat, b_cat, W_new, b_new, x0);
    stream_gemm<<<dim3(MB, 2), 256>>>(des, tweet, b_des, b_tweet, x0);

    // x1 = lrelu(x0 @ W_in + b_in)
    pipe_gemm<<<dim3(MB, 2), 256>>>(x0, 128, 1 << 20, x0, 128,
                                    W_in, b_in, x1, 128, 1);

    const int AGG_BLOCKS = (NNODES + 7) / 8;

    // RGCN layer 1
    aggregate_kernel<<<AGG_BLOCKS, 256>>>(x1, agg);
    pipe_gemm<<<dim3(MB, 2), 256>>>(agg, 256, 256, x1, 128,
                                    wcat1, bias1, x2, 384, 0);

    // RGCN layer 2
    aggregate_kernel<<<AGG_BLOCKS, 256>>>(x2, agg);
    pipe_gemm<<<dim3(MB, 2), 256>>>(agg, 256, 256, x2, 128,
                                    wcat2, bias2, x3, 384, 0);

    // Head
    pipe_gemm<<<dim3(MB, 2), 256>>>(x3, 128, 1 << 20, x3, 128,
                                    W_out1, b_out1, x1, 128, 1);
    final_kernel<<<(NNODES + 255) / 256, 256>>>(x1, W_out2, b_out2, (float*)d_out);
}

// round 7
// speedup vs baseline: 1.4434x; 1.0264x over previous
#include <cuda_runtime.h>
#include <stdint.h>

#define NNODES 50000
#define NEDGES 600000

// ---------------- scratch (static device globals; no dynamic alloc) ----------
__device__ float g_x0[(size_t)NNODES * 128];
__device__ float g_x1[(size_t)NNODES * 128];
__device__ float g_x2[(size_t)NNODES * 128];
__device__ float g_x3[(size_t)NNODES * 128];
__device__ float g_agg[(size_t)NNODES * 256];
__device__ float g_wcat1[384 * 128];
__device__ float g_wcat2[384 * 128];
__device__ float g_wpad[2 * 768 * 32];
__device__ int   g_cnt[NNODES];
__device__ int   g_rowptr[NNODES + 1];
__device__ int   g_cursor[NNODES];
__device__ int   g_adj[NEDGES];

// ---------------- helpers ----------------------------------------------------
typedef unsigned long long ull;

__device__ __forceinline__ float lrelu(float x) { return x > 0.f ? x : 0.01f * x; }

__device__ __forceinline__ void ffma2(ull& d, ull a, ull b, ull c) {
    asm("fma.rn.f32x2 %0, %1, %2, %3;" : "=l"(d) : "l"(a), "l"(b), "l"(c));
}
__device__ __forceinline__ ull dup2(float x) {
    ull r; asm("mov.b64 %0, {%1, %1};" : "=l"(r) : "f"(x)); return r;
}
__device__ __forceinline__ float2 unpk(ull v) {
    float2 r; asm("mov.b64 {%0, %1}, %2;" : "=f"(r.x), "=f"(r.y) : "l"(v)); return r;
}

__device__ __forceinline__ void cp_async16(uint32_t smem, const void* gptr, int bytes) {
    asm volatile("cp.async.cg.shared.global [%0], [%1], 16, %2;"
                 :: "r"(smem), "l"(gptr), "r"(bytes) : "memory");
}
__device__ __forceinline__ void cp_commit() {
    asm volatile("cp.async.commit_group;" ::: "memory");
}
template <int N>
__device__ __forceinline__ void cp_wait() {
    asm volatile("cp.async.wait_group %0;" :: "n"(N) : "memory");
}

// ---------------- pgemm2: C[N,128] = act(A[N,K] @ W[K,128] + b) --------------
// A split: k < ksplit from A1 (lda1), else A2 (lda2). BM=128, BN=64 (grid.y=2),
// BK=16, 256 threads. Register-staged double buffer, 1 sync/chunk,
// round-1 compute layout (A transposed in smem, 25 instr/kk).
__global__ __launch_bounds__(256) void pgemm2(
    const float* __restrict__ A1, int lda1, int ksplit,
    const float* __restrict__ A2, int lda2,
    const float* __restrict__ W,          // [K,128] row-major
    const float* __restrict__ bias,       // [128]
    float* __restrict__ C,                // [N,128]
    int K, int relu)
{
    constexpr int LDA = 132, LDB = 68;
    __shared__ __align__(16) float As[2][16 * LDA];
    __shared__ __align__(16) float Bs[2][16 * LDB];

    const int tid = threadIdx.x;
    const int tx = tid & 15;          // col group (4 cols)
    const int ty = tid >> 4;          // row group (8 rows)
    const int bm = blockIdx.x * 128;
    const int bn = blockIdx.y * 64;

    // A staging mapping
    const int arow = tid >> 1;            // 0..127
    const int koff = (tid & 1) * 8;       // 0 or 8
    int gr = bm + arow;
    const bool rvalid = gr < NNODES;
    if (!rvalid) gr = NNODES - 1;
    // B staging mapping
    const int bkr = tid >> 4;             // 0..15
    const int bu  = tid & 15;             // 0..15

    const int NCH = K / 16;

    auto ldgA = [&](int c, float4& x, float4& y) {
        int k0 = c * 16;
        const float* A; int lda, kb;
        if (k0 < ksplit) { A = A1; lda = lda1; kb = k0; }
        else             { A = A2; lda = lda2; kb = k0 - ksplit; }
        const float* p = A + (size_t)gr * lda + kb + koff;
        x = *reinterpret_cast<const float4*>(p);
        y = *reinterpret_cast<const float4*>(p + 4);
    };
    auto ldgB = [&](int c, float4& b) {
        b = *reinterpret_cast<const float4*>(
            W + (size_t)(c * 16 + bkr) * 128 + bn + bu * 4);
    };
    auto stsA = [&](int s, const float4& x, const float4& y) {
        float* base = &As[s][0];
        base[(koff + 0) * LDA + arow] = x.x;
        base[(koff + 1) * LDA + arow] = x.y;
        base[(koff + 2) * LDA + arow] = x.z;
        base[(koff + 3) * LDA + arow] = x.w;
        base[(koff + 4) * LDA + arow] = y.x;
        base[(koff + 5) * LDA + arow] = y.y;
        base[(koff + 6) * LDA + arow] = y.z;
        base[(koff + 7) * LDA + arow] = y.w;
    };
    auto stsB = [&](int s, const float4& b) {
        *reinterpret_cast<float4*>(&Bs[s][bkr * LDB + bu * 4]) = b;
    };

    ull acc[4][4];
#pragma unroll
    for (int p = 0; p < 4; p++)
#pragma unroll
        for (int j = 0; j < 4; j++) acc[p][j] = 0ull;

    // prologue: stage chunk 0, prefetch chunk 1 into regs
    float4 ax, ay, bf;
    ldgA(0, ax, ay); ldgB(0, bf);
    stsA(0, ax, ay); stsB(0, bf);
    if (NCH > 1) { ldgA(1, ax, ay); ldgB(1, bf); }
    __syncthreads();

    for (int c = 0; c < NCH; c++) {
        const int s = c & 1;
        if (c + 1 < NCH) { stsA(s ^ 1, ax, ay); stsB(s ^ 1, bf); }
        if (c + 2 < NCH) { ldgA(c + 2, ax, ay); ldgB(c + 2, bf); }

        const float* as = &As[s][0];
        const float* bs = &Bs[s][0];
#pragma unroll
        for (int kk = 0; kk < 16; kk++) {
            ull a[4];
#pragma unroll
            for (int p = 0; p < 4; p++)
                a[p] = *reinterpret_cast<const ull*>(as + kk * LDA + ty * 8 + 2 * p);
            float4 b = *reinterpret_cast<const float4*>(bs + kk * LDB + tx * 4);
            ull b0 = dup2(b.x), b1 = dup2(b.y), b2 = dup2(b.z), b3 = dup2(b.w);
#pragma unroll
            for (int p = 0; p < 4; p++) {
                ffma2(acc[p][0], a[p], b0, acc[p][0]);
                ffma2(acc[p][1], a[p], b1, acc[p][1]);
                ffma2(acc[p][2], a[p], b2, acc[p][2]);
                ffma2(acc[p][3], a[p], b3, acc[p][3]);
            }
        }
        __syncthreads();
    }

    // epilogue
    const int c0 = bn + tx * 4;
    const float4 b4 = *reinterpret_cast<const float4*>(bias + c0);
#pragma unroll
    for (int p = 0; p < 4; p++) {
        int re = bm + ty * 8 + 2 * p;
        float2 v0 = unpk(acc[p][0]);
        float2 v1 = unpk(acc[p][1]);
        float2 v2 = unpk(acc[p][2]);
        float2 v3 = unpk(acc[p][3]);
        float4 oe, oo;
        oe.x = v0.x + b4.x; oe.y = v1.x + b4.y; oe.z = v2.x + b4.z; oe.w = v3.x + b4.w;
        oo.x = v0.y + b4.x; oo.y = v1.y + b4.y; oo.z = v2.y + b4.z; oo.w = v3.y + b4.w;
        if (relu) {
            oe.x = lrelu(oe.x); oe.y = lrelu(oe.y); oe.z = lrelu(oe.z); oe.w = lrelu(oe.w);
            oo.x = lrelu(oo.x); oo.y = lrelu(oo.y); oo.z = lrelu(oo.z); oo.w = lrelu(oo.w);
        }
        if (re < NNODES)
            *reinterpret_cast<float4*>(C + (size_t)re * 128 + c0) = oe;
        if (re + 1 < NNODES)
            *reinterpret_cast<float4*>(C + (size_t)(re + 1) * 128 + c0) = oo;
    }
}

// ---------------- streaming GEMM for des/tweet (K=768, NC<=32) ---------------
__global__ __launch_bounds__(256) void stream_gemm(
    const float* __restrict__ A0, const float* __restrict__ A1,
    const float* __restrict__ bias0, const float* __restrict__ bias1,
    float* __restrict__ C)
{
    constexpr int K = 768, BM = 128, BK = 32, LDA = 36;
    __shared__ float As[2][BM * LDA];
    __shared__ float Bs[2][BK * 32];

    const int y = blockIdx.y;
    const float* A    = y ? A1 : A0;
    const float* bias = y ? bias1 : bias0;
    const float* Wp   = g_wpad + y * (768 * 32);
    const int col_off = y ? 25 : 0;
    const int NC      = y ? 28 : 25;

    const int tid = threadIdx.x;
    const int tx = tid & 7;
    const int ty = tid >> 3;
    const int bm = blockIdx.x * BM;

    uint32_t as_u[2], bs_u[2];
    as_u[0] = (uint32_t)__cvta_generic_to_shared(&As[0][0]);
    as_u[1] = (uint32_t)__cvta_generic_to_shared(&As[1][0]);
    bs_u[0] = (uint32_t)__cvta_generic_to_shared(&Bs[0][0]);
    bs_u[1] = (uint32_t)__cvta_generic_to_shared(&Bs[1][0]);

    ull acc[4][2];
#pragma unroll
    for (int i = 0; i < 4; i++) { acc[i][0] = 0ull; acc[i][1] = 0ull; }

    auto stage = [&](int s, int k0) {
#pragma unroll
        for (int j = 0; j < 4; j++) {
            int unit = tid + j * 256;
            int row = unit >> 3;
            int seg = unit & 7;
            int gr = bm + row;
            cp_async16(as_u[s] + (uint32_t)(row * (LDA * 4) + seg * 16),
                       A + (size_t)gr * K + k0 + seg * 4,
                       gr < NNODES ? 16 : 0);
        }
        {
            int kr = tid >> 3;
            int seg = tid & 7;
            cp_async16(bs_u[s] + (uint32_t)(kr * 128 + seg * 16),
                       Wp + (size_t)(k0 + kr) * 32 + seg * 4, 16);
        }
    };

    stage(0, 0);
    cp_commit();

    for (int c = 0; c < K / BK; c++) {
        const int s = c & 1;
        if (c + 1 < K / BK) {
            stage(s ^ 1, (c + 1) * BK);
            cp_commit();
            cp_wait<1>();
        } else {
            cp_wait<0>();
        }
        __syncthreads();

        const float* as = &As[s][0];
        const float* bs = &Bs[s][0];
#pragma unroll
        for (int kk = 0; kk < BK; kk++) {
            ull b01 = *reinterpret_cast<const ull*>(bs + kk * 32 + tx * 4);
            ull b23 = *reinterpret_cast<const ull*>(bs + kk * 32 + tx * 4 + 2);
#pragma unroll
            for (int i = 0; i < 4; i++) {
                float a = as[(ty + 32 * i) * LDA + kk];
                ull a2 = dup2(a);
                ffma2(acc[i][0], a2, b01, acc[i][0]);
                ffma2(acc[i][1], a2, b23, acc[i][1]);
            }
        }
        __syncthreads();
    }

    float bv[4];
#pragma unroll
    for (int j = 0; j < 4; j++) {
        int gc = tx * 4 + j;
        bv[j] = (gc < NC) ? bias[gc] : 0.f;
    }
#pragma unroll
    for (int i = 0; i < 4; i++) {
        int row = bm + ty + 32 * i;
        if (row >= NNODES) continue;
        float2 v01 = unpk(acc[i][0]);
        float2 v23 = unpk(acc[i][1]);
        float o[4] = {v01.x, v01.y, v23.x, v23.y};
        float* cr = C + (size_t)row * 128 + col_off;
#pragma unroll
        for (int j = 0; j < 4; j++) {
            int gc = tx * 4 + j;
            if (gc < NC) cr[gc] = lrelu(o[j] + bv[j]);
        }
    }
}

// ---------------- prep: pad W, build both wcat, zero cnt ---------------------
__global__ void prep_kernel(const float* __restrict__ Wd,
                            const float* __restrict__ Wt,
                            const float* __restrict__ relw1,
                            const float* __restrict__ rootw1,
                            const float* __restrict__ relw2,
                            const float* __restrict__ rootw2) {
    int i = blockIdx.x * blockDim.x + threadIdx.x;
    if (i < 2 * 768 * 32) {
        int which = i >= 768 * 32;
        int r = i - which * 768 * 32;
        int k = r >> 5, j = r & 31;
        float v = 0.f;
        if (!which) { if (j < 25) v = Wd[k * 25 + j]; }
        else        { if (j < 28) v = Wt[k * 28 + j]; }
        g_wpad[i] = v;
    }
    if (i < 49152) {
        g_wcat1[i] = (i < 32768) ? relw1[i] : rootw1[i - 32768];
        g_wcat2[i] = (i < 32768) ? relw2[i] : rootw2[i - 32768];
    }
    if (i < NNODES) g_cnt[i] = 0;
}

// ---------------- small-K feature columns (num/cat/new -> x0 cols 53..127) ---
__global__ void feat_small_kernel(
    const float* __restrict__ numf, const float* __restrict__ catf,
    const float* __restrict__ nf,
    const float* __restrict__ Wn, const float* __restrict__ bn,
    const float* __restrict__ Wc, const float* __restrict__ bc,
    const float* __restrict__ Ww, const float* __restrict__ bw,
    float* __restrict__ x0)
{
    __shared__ float sWn[7 * 25], sbn[25], sWc[11 * 25], sbc[25], sWw[25], sbw[25];
    int tid = threadIdx.x;
    for (int i = tid; i < 7 * 25; i += blockDim.x) sWn[i] = Wn[i];
    for (int i = tid; i < 11 * 25; i += blockDim.x) sWc[i] = Wc[i];
    for (int i = tid; i < 25; i += blockDim.x) {
        sbn[i] = bn[i]; sbc[i] = bc[i]; sWw[i] = Ww[i]; sbw[i] = bw[i];
    }
    __syncthreads();

    int r = blockIdx.x * blockDim.x + tid;
    if (r >= NNODES) return;

    float nv[7], cv[11];
#pragma unroll
    for (int k = 0; k < 7; k++) nv[k] = numf[(size_t)r * 7 + k];
#pragma unroll
    for (int k = 0; k < 11; k++) cv[k] = catf[(size_t)r * 11 + k];
    float wv = nf[r];

    float* out = x0 + (size_t)r * 128;
#pragma unroll
    for (int j = 0; j < 25; j++) {
        float a = sbn[j];
#pragma unroll
        for (int k = 0; k < 7; k++) a += nv[k] * sWn[k * 25 + j];
        out[53 + j] = lrelu(a);
    }
#pragma unroll
    for (int j = 0; j < 25; j++) {
        float a = sbc[j];
#pragma unroll
        for (int k = 0; k < 11; k++) a += cv[k] * sWc[k * 25 + j];
        out[78 + j] = lrelu(a);
    }
#pragma unroll
    for (int j = 0; j < 25; j++)
        out[103 + j] = lrelu(wv * sWw[j] + sbw[j]);
}

// ---------------- CSR build ---------------------------------------------------
__global__ void hist_kernel(const int* __restrict__ ei) {
    int e = blockIdx.x * blockDim.x + threadIdx.x;
    if (e < NEDGES) atomicAdd(&g_cnt[ei[NEDGES + e]], 1);
}

__global__ void scan_kernel() {
    __shared__ int wsum[32];
    __shared__ int carry;
    int tid = threadIdx.x, lane = tid & 31, wid = tid >> 5;
    if (tid == 0) carry = 0;
    __syncthreads();
    for (int base = 0; base < NNODES; base += 1024) {
        int i = base + tid;
        int v = (i < NNODES) ? g_cnt[i] : 0;
        int x = v;
#pragma unroll
        for (int o = 1; o < 32; o <<= 1) {
            int y = __shfl_up_sync(0xffffffffu, x, o);
            if (lane >= o) x += y;
        }
        if (lane == 31) wsum[wid] = x;
        __syncthreads();
        if (wid == 0) {
            int s = wsum[lane];
#pragma unroll
            for (int o = 1; o < 32; o <<= 1) {
                int y = __shfl_up_sync(0xffffffffu, s, o);
                if (lane >= o) s += y;
            }
            wsum[lane] = s;
        }
        __syncthreads();
        int c = carry;
        int woff = wid ? wsum[wid - 1] : 0;
        int excl = c + woff + x - v;
        if (i < NNODES) { g_rowptr[i] = excl; g_cursor[i] = excl; }
        int total = wsum[31];
        __syncthreads();
        if (tid == 0) carry = c + total;
        __syncthreads();
    }
    if (threadIdx.x == 0) g_rowptr[NNODES] = NEDGES;
}

__global__ void fill_kernel(const int* __restrict__ ei, const int* __restrict__ et) {
    int e = blockIdx.x * blockDim.x + threadIdx.x;
    if (e < NEDGES) {
        int s = ei[e];
        int d = ei[NEDGES + e];
        int t = et[e];
        int p = atomicAdd(&g_cursor[d], 1);
        g_adj[p] = s | (t << 30);
    }
}

// ---------------- aggregation: agg = [sumA/deg | sumB/deg]  [N,256] ----------
__global__ __launch_bounds__(256) void aggregate_kernel(
    const float* __restrict__ xin, float* __restrict__ agg)
{
    const int w = (blockIdx.x * blockDim.x + threadIdx.x) >> 5;
    const int lane = threadIdx.x & 31;
    if (w >= NNODES) return;
    const int beg = g_rowptr[w], end = g_rowptr[w + 1];
    const int deg = end - beg;

    float4 aA = make_float4(0.f, 0.f, 0.f, 0.f);
    float4 aB = make_float4(0.f, 0.f, 0.f, 0.f);

    for (int t0 = 0; t0 < deg; t0 += 32) {
        int e = beg + t0 + lane;
        int pk = (e < end) ? g_adj[e] : 0;
        int nv = min(deg - t0, 32);
        int j = 0;
        for (; j + 4 <= nv; j += 4) {
            int p0 = __shfl_sync(0xffffffffu, pk, j);
            int p1 = __shfl_sync(0xffffffffu, pk, j + 1);
            int p2 = __shfl_sync(0xffffffffu, pk, j + 2);
            int p3 = __shfl_sync(0xffffffffu, pk, j + 3);
            float4 v0 = *reinterpret_cast<const float4*>(
                xin + (size_t)(p0 & 0x3FFFFFFF) * 128 + lane * 4);
            float4 v1 = *reinterpret_cast<const float4*>(
                xin + (size_t)(p1 & 0x3FFFFFFF) * 128 + lane * 4);
            float4 v2 = *reinterpret_cast<const float4*>(
                xin + (size_t)(p2 & 0x3FFFFFFF) * 128 + lane * 4);
            float4 v3 = *reinterpret_cast<const float4*>(
                xin + (size_t)(p3 & 0x3FFFFFFF) * 128 + lane * 4);
            if (p0 >> 30) { aB.x += v0.x; aB.y += v0.y; aB.z += v0.z; aB.w += v0.w; }
            else          { aA.x += v0.x; aA.y += v0.y; aA.z += v0.z; aA.w += v0.w; }
            if (p1 >> 30) { aB.x += v1.x; aB.y += v1.y; aB.z += v1.z; aB.w += v1.w; }
            else          { aA.x += v1.x; aA.y += v1.y; aA.z += v1.z; aA.w += v1.w; }
            if (p2 >> 30) { aB.x += v2.x; aB.y += v2.y; aB.z += v2.z; aB.w += v2.w; }
            else          { aA.x += v2.x; aA.y += v2.y; aA.z += v2.z; aA.w += v2.w; }
            if (p3 >> 30) { aB.x += v3.x; aB.y += v3.y; aB.z += v3.z; aB.w += v3.w; }
            else          { aA.x += v3.x; aA.y += v3.y; aA.z += v3.z; aA.w += v3.w; }
        }
        for (; j < nv; j++) {
            int p = __shfl_sync(0xffffffffu, pk, j);
            float4 v = *reinterpret_cast<const float4*>(
                xin + (size_t)(p & 0x3FFFFFFF) * 128 + lane * 4);
            if (p >> 30) { aB.x += v.x; aB.y += v.y; aB.z += v.z; aB.w += v.w; }
            else         { aA.x += v.x; aA.y += v.y; aA.z += v.z; aA.w += v.w; }
        }
    }

    const float s = 1.f / (float)(deg > 0 ? deg : 1);
    float* o = agg + (size_t)w * 256 + lane * 4;
    *reinterpret_cast<float4*>(o) =
        make_float4(aA.x * s, aA.y * s, aA.z * s, aA.w * s);
    *reinterpret_cast<float4*>(o + 128) =
        make_float4(aB.x * s, aB.y * s, aB.z * s, aB.w * s);
}

// ---------------- final: out = x @ W_out2 + b_out2 (N x 2) -------------------
__global__ void final_kernel(const float* __restrict__ x,
                             const float* __restrict__ W,
                             const float* __restrict__ b,
                             float* __restrict__ out) {
    __shared__ float w[256];
    __shared__ float bb[2];
    int tid = threadIdx.x;
    for (int i = tid; i < 256; i += blockDim.x) w[i] = W[i];
    if (tid < 2) bb[tid] = b[tid];
    __syncthreads();
    int r = blockIdx.x * blockDim.x + tid;
    if (r >= NNODES) return;
    float a0 = bb[0], a1 = bb[1];
    const float4* xr = reinterpret_cast<const float4*>(x + (size_t)r * 128);
#pragma unroll
    for (int k4 = 0; k4 < 32; k4++) {
        float4 v = xr[k4];
        int k = k4 * 4;
        a0 += v.x * w[2 * k + 0]; a1 += v.x * w[2 * k + 1];
        a0 += v.y * w[2 * k + 2]; a1 += v.y * w[2 * k + 3];
        a0 += v.z * w[2 * k + 4]; a1 += v.z * w[2 * k + 5];
        a0 += v.w * w[2 * k + 6]; a1 += v.w * w[2 * k + 7];
    }
    out[(size_t)r * 2 + 0] = a0;
    out[(size_t)r * 2 + 1] = a1;
}

// ---------------- launch ------------------------------------------------------
extern "C" void kernel_launch(void* const* d_in, const int* in_sizes, int n_in,
                              void* d_out, int out_size)
{
    const bool setup_order = (in_sizes[5] == 2 * NEDGES);

    const float* des   = (const float*)d_in[0];
    const float* tweet = (const float*)d_in[1];
    const float* numf  = (const float*)d_in[2];
    const float* catf  = (const float*)d_in[3];
    const float* nf    = (const float*)d_in[4];
    const int* ei;
    const int* et;
    int wbase;
    if (setup_order) { ei = (const int*)d_in[5]; et = (const int*)d_in[6]; wbase = 7; }
    else             { ei = (const int*)d_in[27]; et = (const int*)d_in[28]; wbase = 5; }

#define WI(k) ((const float*)d_in[wbase + (k)])
    const float* W_des   = WI(0);  const float* b_des   = WI(1);
    const float* W_tweet = WI(2);  const float* b_tweet = WI(3);
    const float* W_num   = WI(4);  const float* b_num   = WI(5);
    const float* W_cat   = WI(6);  const float* b_cat   = WI(7);
    const float* W_new   = WI(8);  const float* b_new   = WI(9);
    const float* W_in    = WI(10); const float* b_in    = WI(11);
    const float* rel_w1  = WI(12); const float* root_w1 = WI(13); const float* bias1 = WI(14);
    const float* rel_w2  = WI(15); const float* root_w2 = WI(16); const float* bias2 = WI(17);
    const float* W_out1  = WI(18); const float* b_out1  = WI(19);
    const float* W_out2  = WI(20); const float* b_out2  = WI(21);
#undef WI

    float *x0, *x1, *x2, *x3, *agg, *wcat1, *wcat2;
    cudaGetSymbolAddress((void**)&x0, g_x0);
    cudaGetSymbolAddress((void**)&x1, g_x1);
    cudaGetSymbolAddress((void**)&x2, g_x2);
    cudaGetSymbolAddress((void**)&x3, g_x3);
    cudaGetSymbolAddress((void**)&agg, g_agg);
    cudaGetSymbolAddress((void**)&wcat1, g_wcat1);
    cudaGetSymbolAddress((void**)&wcat2, g_wcat2);

    const int MB = (NNODES + 127) / 128;  // 391

    // Launch order arranged so ncu's capture slot (#4) lands on stream_gemm.
    prep_kernel<<<(NNODES + 255) / 256, 256>>>(W_des, W_tweet,
                                               rel_w1, root_w1, rel_w2, root_w2);
    feat_small_kernel<<<(NNODES + 255) / 256, 256>>>(
        numf, catf, nf, W_num, b_num, W_cat, b_cat, W_new, b_new, x0);
    hist_kernel<<<(NEDGES + 255) / 256, 256>>>(ei);
    stream_gemm<<<dim3(MB, 2), 256>>>(des, tweet, b_des, b_tweet, x0);  // slot 4
    scan_kernel<<<1, 1024>>>();
    fill_kernel<<<(NEDGES + 255) / 256, 256>>>(ei, et);

    // x1 = lrelu(x0 @ W_in + b_in)
    pgemm2<<<dim3(MB, 2), 256>>>(x0, 128, 1 << 20, x0, 128,
                                 W_in, b_in, x1, 128, 1);

    const int AGG_BLOCKS = (NNODES + 7) / 8;

    // RGCN layer 1
    aggregate_kernel<<<AGG_BLOCKS, 256>>>(x1, agg);
    pgemm2<<<dim3(MB, 2), 256>>>(agg, 256, 256, x1, 128,
                                 wcat1, bias1, x2, 384, 0);

    // RGCN layer 2
    aggregate_kernel<<<AGG_BLOCKS, 256>>>(x2, agg);
    pgemm2<<<dim3(MB, 2), 256>>>(agg, 256, 256, x2, 128,
                                 wcat2, bias2, x3, 384, 0);

    // Head
    pgemm2<<<dim3(MB, 2), 256>>>(x3, 128, 1 << 20, x3, 128,
                                 W_out1, b_out1, x1, 128, 1);
    final_kernel<<<(NNODES + 255) / 256, 256>>>(x1, W_out2, b_out2, (float*)d_out);
}